// round 1
// baseline (speedup 1.0000x reference)
#include <cuda_runtime.h>

// Problem constants
#define BB   8
#define LL   1024
#define DIN  512
#define HH   8
#define DD   64
#define DOUT 512
#define MM   (BB * LL)   // 8192

// Scratch: projected q, k, v in [B, H, L, D] layout (16 MB each)
__device__ float g_q[BB * HH * LL * DD];
__device__ float g_k[BB * HH * LL * DD];
__device__ float g_v[BB * HH * LL * DD];

// ---------------------------------------------------------------------------
// Fused projection: Y = X @ W for (Q,K,V) via blockIdx.z.
// X: [8192, 512] row-major. W: [512, 512] row-major (K x N).
// Output written as [B, H, L, D]; block tile 64(M) x 64(N), so blockIdx.x == head.
// Thread block 16x16; micro-tile 4(M, contiguous) x 4(N, strided by 16).
// ---------------------------------------------------------------------------
__global__ __launch_bounds__(256, 4)
void proj_kernel(const float* __restrict__ Xq, const float* __restrict__ Xk,
                 const float* __restrict__ Xv,
                 const float* __restrict__ Wq, const float* __restrict__ Wk,
                 const float* __restrict__ Wv)
{
    const float* X;
    const float* W;
    float* out;
    if (blockIdx.z == 0)      { X = Xq; W = Wq; out = g_q; }
    else if (blockIdx.z == 1) { X = Xk; W = Wk; out = g_k; }
    else                      { X = Xv; W = Wv; out = g_v; }

    __shared__ float Xs[16][68];  // [k][m], padded
    __shared__ float Ws[16][68];  // [k][n], padded (float4-aligned pad)

    const int tx = threadIdx.x, ty = threadIdx.y;
    const int tid = ty * 16 + tx;
    const int m0 = blockIdx.y * 64;
    const int h  = blockIdx.x;          // head
    const int n0 = h * 64;

    float acc[4][4] = {};

    for (int k0 = 0; k0 < DIN; k0 += 16) {
        // Load X tile: 64 rows x 16 k. One float4 per thread, scatter to Xs[k][m].
        {
            const int r  = tid >> 2;           // 0..63
            const int c4 = (tid & 3) * 4;      // 0,4,8,12
            const float4 x = *(const float4*)&X[(size_t)(m0 + r) * DIN + k0 + c4];
            Xs[c4 + 0][r] = x.x;
            Xs[c4 + 1][r] = x.y;
            Xs[c4 + 2][r] = x.z;
            Xs[c4 + 3][r] = x.w;
        }
        // Load W tile: 16 k x 64 n. One float4 per thread.
        {
            const int r  = tid >> 4;           // 0..15
            const int c4 = (tid & 15) * 4;     // 0..60
            *(float4*)&Ws[r][c4] = *(const float4*)&W[(size_t)(k0 + r) * DOUT + n0 + c4];
        }
        __syncthreads();

        #pragma unroll
        for (int k = 0; k < 16; k++) {
            float a[4], b[4];
            #pragma unroll
            for (int i = 0; i < 4; i++) a[i] = Xs[k][ty * 4 + i];        // broadcast
            #pragma unroll
            for (int j = 0; j < 4; j++) b[j] = Ws[k][tx + 16 * j];       // conflict-free
            #pragma unroll
            for (int i = 0; i < 4; i++)
                #pragma unroll
                for (int j = 0; j < 4; j++)
                    acc[i][j] += a[i] * b[j];
        }
        __syncthreads();
    }

    // Write out in [B, H, L, D] layout. d = tx + 16*j (coalesced per j).
    #pragma unroll
    for (int i = 0; i < 4; i++) {
        const int m = m0 + ty * 4 + i;
        const int b = m >> 10;       // m / 1024
        const int l = m & 1023;      // m % 1024
        float* o = &out[((size_t)(b * HH + h) * LL + l) * DD];
        #pragma unroll
        for (int j = 0; j < 4; j++)
            o[tx + 16 * j] = acc[i][j];
    }
}

// ---------------------------------------------------------------------------
// Flash attention (causal), fp32. One block = one (b,h) x 64-query tile.
// Block 16x16 threads. Thread micro-tile: rows ty*4+i, cols tx+16*j (strided).
// Online softmax; key-tile loop bounded by causality (jt <= it).
// Dynamic smem: Qs/Ks/Vs [64][65] + Ps [64][68].
// ---------------------------------------------------------------------------
#define QKV_PAD 65
#define P_PAD   68
#define SMEM_ATTN ((3 * 64 * QKV_PAD + 64 * P_PAD) * (int)sizeof(float))

__global__ __launch_bounds__(256, 3)
void attn_kernel(float* __restrict__ out)
{
    extern __shared__ float sm[];
    float* Qs = sm;
    float* Ks = Qs + 64 * QKV_PAD;
    float* Vs = Ks + 64 * QKV_PAD;
    float* Ps = Vs + 64 * QKV_PAD;

    const int it = blockIdx.x;          // query tile 0..15
    const int bh = blockIdx.y;          // 0..63
    const int b  = bh >> 3;
    const int h  = bh & 7;

    const float* Qb = g_q + (size_t)bh * LL * DD;
    const float* Kb = g_k + (size_t)bh * LL * DD;
    const float* Vb = g_v + (size_t)bh * LL * DD;

    const int tx = threadIdx.x, ty = threadIdx.y;
    const int tid = ty * 16 + tx;
    const float scale = 0.125f;  // 1/sqrt(64)

    // Load Q tile (64x64): each thread 4 float4 global loads, scalar smem stores.
    for (int idx = tid; idx < 64 * 16; idx += 256) {
        const int r = idx >> 4;
        const int c = (idx & 15) * 4;
        const float4 v = *(const float4*)&Qb[(size_t)(it * 64 + r) * DD + c];
        Qs[r * QKV_PAD + c + 0] = v.x;
        Qs[r * QKV_PAD + c + 1] = v.y;
        Qs[r * QKV_PAD + c + 2] = v.z;
        Qs[r * QKV_PAD + c + 3] = v.w;
    }

    float o[4][4] = {};
    float m_i[4], l_i[4];
    #pragma unroll
    for (int i = 0; i < 4; i++) { m_i[i] = -1e30f; l_i[i] = 0.0f; }

    for (int jt = 0; jt <= it; jt++) {
        __syncthreads();  // prior iter done reading Ks/Vs/Ps; Q load done (jt=0)

        // Load K and V tiles
        for (int idx = tid; idx < 64 * 16; idx += 256) {
            const int r = idx >> 4;
            const int c = (idx & 15) * 4;
            const float4 kv = *(const float4*)&Kb[(size_t)(jt * 64 + r) * DD + c];
            Ks[r * QKV_PAD + c + 0] = kv.x;
            Ks[r * QKV_PAD + c + 1] = kv.y;
            Ks[r * QKV_PAD + c + 2] = kv.z;
            Ks[r * QKV_PAD + c + 3] = kv.w;
            const float4 vv = *(const float4*)&Vb[(size_t)(jt * 64 + r) * DD + c];
            Vs[r * QKV_PAD + c + 0] = vv.x;
            Vs[r * QKV_PAD + c + 1] = vv.y;
            Vs[r * QKV_PAD + c + 2] = vv.z;
            Vs[r * QKV_PAD + c + 3] = vv.w;
        }
        __syncthreads();

        // S = Q K^T  (rows ty*4+i, cols tx+16*j)
        float s[4][4] = {};
        #pragma unroll 8
        for (int dk = 0; dk < 64; dk++) {
            float a[4], bq[4];
            #pragma unroll
            for (int i = 0; i < 4; i++) a[i] = Qs[(ty * 4 + i) * QKV_PAD + dk];
            #pragma unroll
            for (int j = 0; j < 4; j++) bq[j] = Ks[(tx + 16 * j) * QKV_PAD + dk];
            #pragma unroll
            for (int i = 0; i < 4; i++)
                #pragma unroll
                for (int j = 0; j < 4; j++)
                    s[i][j] += a[i] * bq[j];
        }

        // Scale + causal mask (only diagonal tile has masked entries)
        #pragma unroll
        for (int i = 0; i < 4; i++) {
            const int qr = it * 64 + ty * 4 + i;
            #pragma unroll
            for (int j = 0; j < 4; j++) {
                const int kc = jt * 64 + tx + 16 * j;
                s[i][j] = (kc > qr) ? -1e30f : s[i][j] * scale;
            }
        }

        // Online softmax per row; write P to smem; rescale O
        #pragma unroll
        for (int i = 0; i < 4; i++) {
            float mx = fmaxf(fmaxf(s[i][0], s[i][1]), fmaxf(s[i][2], s[i][3]));
            #pragma unroll
            for (int off = 1; off < 16; off <<= 1)
                mx = fmaxf(mx, __shfl_xor_sync(0xffffffffu, mx, off));
            const float mnew = fmaxf(m_i[i], mx);
            const float f = __expf(m_i[i] - mnew);
            float rs = 0.0f;
            #pragma unroll
            for (int j = 0; j < 4; j++) {
                const float p = __expf(s[i][j] - mnew);
                Ps[(ty * 4 + i) * P_PAD + tx + 16 * j] = p;
                rs += p;
            }
            #pragma unroll
            for (int off = 1; off < 16; off <<= 1)
                rs += __shfl_xor_sync(0xffffffffu, rs, off);
            l_i[i] = l_i[i] * f + rs;
            m_i[i] = mnew;
            #pragma unroll
            for (int j = 0; j < 4; j++) o[i][j] *= f;
        }
        __syncthreads();

        // O += P @ V  (O rows ty*4+i, cols tx+16*j)
        #pragma unroll 8
        for (int c = 0; c < 64; c++) {
            float p[4], v[4];
            #pragma unroll
            for (int i = 0; i < 4; i++) p[i] = Ps[(ty * 4 + i) * P_PAD + c];
            #pragma unroll
            for (int j = 0; j < 4; j++) v[j] = Vs[c * QKV_PAD + tx + 16 * j];
            #pragma unroll
            for (int i = 0; i < 4; i++)
                #pragma unroll
                for (int j = 0; j < 4; j++)
                    o[i][j] += p[i] * v[j];
        }
    }

    // Final normalize and store: out[b, l, h*64 + d]
    #pragma unroll
    for (int i = 0; i < 4; i++) {
        const int l = it * 64 + ty * 4 + i;
        const float inv = 1.0f / l_i[i];
        float* op = &out[((size_t)(b * LL + l)) * DOUT + h * DD];
        #pragma unroll
        for (int j = 0; j < 4; j++)
            op[tx + 16 * j] = o[i][j] * inv;
    }
}

// ---------------------------------------------------------------------------
extern "C" void kernel_launch(void* const* d_in, const int* in_sizes, int n_in,
                              void* d_out, int out_size)
{
    const float* Qseq = (const float*)d_in[0];
    const float* Kseq = (const float*)d_in[1];
    const float* Vseq = (const float*)d_in[2];
    const float* WQ   = (const float*)d_in[3];
    const float* WK   = (const float*)d_in[4];
    const float* WV   = (const float*)d_in[5];
    float* out = (float*)d_out;

    cudaFuncSetAttribute(attn_kernel,
                         cudaFuncAttributeMaxDynamicSharedMemorySize, SMEM_ATTN);

    dim3 pblk(16, 16);
    dim3 pgrd(DOUT / 64, MM / 64, 3);   // (8, 128, 3)
    proj_kernel<<<pgrd, pblk>>>(Qseq, Kseq, Vseq, WQ, WK, WV);

    dim3 ablk(16, 16);
    dim3 agrd(LL / 64, BB * HH);        // (16, 64)
    attn_kernel<<<agrd, ablk, SMEM_ATTN>>>(out);
}

// round 3
// speedup vs baseline: 1.5102x; 1.5102x over previous
#include <cuda_runtime.h>
#include <cstdint>

// Problem constants
#define BB   8
#define LL   1024
#define DIN  512
#define HH   8
#define DD   64
#define DOUT 512
#define MM   (BB * LL)   // 8192

// Scratch: projected q, k, v in [B, H, L, D] layout (16 MB each)
__device__ float g_q[BB * HH * LL * DD];
__device__ float g_k[BB * HH * LL * DD];
__device__ float g_v[BB * HH * LL * DD];
// Transposed weights: Wt[n][k] = W[k][n], 3 matrices
__device__ float g_wt[3 * DIN * DOUT];

// ===========================================================================
// mma.sync helpers (sm_80+ PTX — valid on sm_103 family target)
// ===========================================================================
__device__ __forceinline__ uint32_t f2tf32(float f) {
    uint32_t r;
    asm("cvt.rna.tf32.f32 %0, %1;" : "=r"(r) : "f"(f));
    return r;
}

__device__ __forceinline__ void mma_tf32_16n8k8(float& d0, float& d1, float& d2, float& d3,
                                                uint32_t a0, uint32_t a1, uint32_t a2, uint32_t a3,
                                                uint32_t b0, uint32_t b1) {
    asm volatile(
        "mma.sync.aligned.m16n8k8.row.col.f32.tf32.tf32.f32 "
        "{%0,%1,%2,%3}, {%4,%5,%6,%7}, {%8,%9}, {%0,%1,%2,%3};"
        : "+f"(d0), "+f"(d1), "+f"(d2), "+f"(d3)
        : "r"(a0), "r"(a1), "r"(a2), "r"(a3), "r"(b0), "r"(b1));
}

__device__ __forceinline__ uint32_t smem_u32(const void* p) {
    uint32_t a;
    asm("{ .reg .u64 t; cvta.to.shared.u64 t, %1; cvt.u32.u64 %0, t; }"
        : "=r"(a) : "l"(p));
    return a;
}

#define CP_ASYNC16(dst_u32, src_ptr) \
    asm volatile("cp.async.cg.shared.global [%0], [%1], 16;" :: "r"(dst_u32), "l"(src_ptr))
#define CP_COMMIT()  asm volatile("cp.async.commit_group;" ::: "memory")
#define CP_WAIT0()   asm volatile("cp.async.wait_group 0;" ::: "memory")

// ===========================================================================
// Weight transpose: Wt[n][k] = W[k][n]
// ===========================================================================
__global__ void transpose_w(const float* __restrict__ Wq,
                            const float* __restrict__ Wk,
                            const float* __restrict__ Wv)
{
    const float* W = (blockIdx.z == 0) ? Wq : (blockIdx.z == 1) ? Wk : Wv;
    float* Wt = g_wt + (size_t)blockIdx.z * DIN * DOUT;

    __shared__ float t[32][33];
    const int tx = threadIdx.x, ty = threadIdx.y;
    int x = blockIdx.x * 32 + tx;   // col in W (n)
    int y = blockIdx.y * 32 + ty;   // row in W (k)
    #pragma unroll
    for (int j = 0; j < 32; j += 8)
        t[ty + j][tx] = W[(size_t)(y + j) * DOUT + x];
    __syncthreads();
    x = blockIdx.y * 32 + tx;       // col in Wt (k)
    y = blockIdx.x * 32 + ty;       // row in Wt (n)
    #pragma unroll
    for (int j = 0; j < 32; j += 8)
        Wt[(size_t)(y + j) * DIN + x] = t[tx][ty + j];
}

// ===========================================================================
// tf32 mma.sync projection: Y[8192,512] = X[8192,512] @ W[512,512]
// CTA 128x128, 8 warps of 32(M)x64(N). K tiles of 32, double-buffered cp.async.
// smem tiles padded to 36 floats/row => conflict-free fragment LDS.
// grid = (DOUT/128=4, MM/128=64, 3), block = 256.
// ===========================================================================
#define PTM 128
#define PTN 128
#define PTK 32
#define PPAD 36
#define PKT  (DIN / PTK)   // 16

#define A_WORDS (PTM * PPAD)            // 4608 floats
#define B_WORDS (PTN * PPAD)
#define SMEM_PROJ ((2 * (A_WORDS + B_WORDS)) * (int)sizeof(float))  // 73728 B

__global__ __launch_bounds__(256)
void proj_mma_kernel(const float* __restrict__ Xq, const float* __restrict__ Xk,
                     const float* __restrict__ Xv)
{
    extern __shared__ float sp[];
    float* As[2] = { sp,                sp + A_WORDS };
    float* Bs[2] = { sp + 2 * A_WORDS,  sp + 2 * A_WORDS + B_WORDS };

    const float* X;
    float* out;
    if (blockIdx.z == 0)      { X = Xq; out = g_q; }
    else if (blockIdx.z == 1) { X = Xk; out = g_k; }
    else                      { X = Xv; out = g_v; }
    const float* Wt = g_wt + (size_t)blockIdx.z * DIN * DOUT;

    const int tid  = threadIdx.x;
    const int wid  = tid >> 5;
    const int lane = tid & 31;
    const int wm   = wid & 3;       // 4 warps along M (32 rows each)
    const int wn   = wid >> 2;      // 2 warps along N (64 cols each)
    const int m0   = blockIdx.y * PTM;
    const int n0   = blockIdx.x * PTN;

    const int lr = lane >> 2;       // 0..7
    const int lc = lane & 3;        // 0..3

    // Per-thread load slots: 4 float4 per tile for A, 4 for B.
    // idx = i*256 + tid ; row = idx>>3 (0..127), c4 = idx&7 (k/4)
    uint32_t a_dst[4], b_dst[4];
    const float* a_src[4];
    const float* b_src[4];
    #pragma unroll
    for (int i = 0; i < 4; i++) {
        const int idx = i * 256 + tid;
        const int r   = idx >> 3;
        const int c4  = idx & 7;
        a_dst[i] = (uint32_t)((r * PPAD + c4 * 4) * 4);
        b_dst[i] = a_dst[i];
        a_src[i] = &X [(size_t)(m0 + r) * DIN + c4 * 4];
        b_src[i] = &Wt[(size_t)(n0 + r) * DIN + c4 * 4];
    }
    const uint32_t sa[2] = { smem_u32(As[0]), smem_u32(As[1]) };
    const uint32_t sb[2] = { smem_u32(Bs[0]), smem_u32(Bs[1]) };

    float acc[2][8][4];
    #pragma unroll
    for (int mt = 0; mt < 2; mt++)
        #pragma unroll
        for (int nt = 0; nt < 8; nt++)
            #pragma unroll
            for (int q = 0; q < 4; q++) acc[mt][nt][q] = 0.0f;

    // Prologue: load tile 0
    #pragma unroll
    for (int i = 0; i < 4; i++) {
        CP_ASYNC16(sa[0] + a_dst[i], a_src[i]);
        CP_ASYNC16(sb[0] + b_dst[i], b_src[i]);
    }
    CP_COMMIT();
    CP_WAIT0();
    __syncthreads();

    for (int kt = 0; kt < PKT; kt++) {
        const int cur = kt & 1;
        // Prefetch next tile
        if (kt + 1 < PKT) {
            const int nxt = cur ^ 1;
            const int koff = (kt + 1) * PTK;
            #pragma unroll
            for (int i = 0; i < 4; i++) {
                CP_ASYNC16(sa[nxt] + a_dst[i], a_src[i] + koff);
                CP_ASYNC16(sb[nxt] + b_dst[i], b_src[i] + koff);
            }
            CP_COMMIT();
        }

        const float* A = As[cur];
        const float* B = Bs[cur];
        #pragma unroll
        for (int ks = 0; ks < 4; ks++) {
            const int kb = ks * 8;
            uint32_t af[2][4];
            #pragma unroll
            for (int mt = 0; mt < 2; mt++) {
                const int rb = wm * 32 + mt * 16 + lr;
                af[mt][0] = f2tf32(A[ rb      * PPAD + kb + lc    ]);
                af[mt][1] = f2tf32(A[(rb + 8) * PPAD + kb + lc    ]);
                af[mt][2] = f2tf32(A[ rb      * PPAD + kb + lc + 4]);
                af[mt][3] = f2tf32(A[(rb + 8) * PPAD + kb + lc + 4]);
            }
            uint32_t bf[8][2];
            #pragma unroll
            for (int nt = 0; nt < 8; nt++) {
                const int nb = wn * 64 + nt * 8 + lr;
                bf[nt][0] = f2tf32(B[nb * PPAD + kb + lc    ]);
                bf[nt][1] = f2tf32(B[nb * PPAD + kb + lc + 4]);
            }
            #pragma unroll
            for (int mt = 0; mt < 2; mt++)
                #pragma unroll
                for (int nt = 0; nt < 8; nt++)
                    mma_tf32_16n8k8(acc[mt][nt][0], acc[mt][nt][1],
                                    acc[mt][nt][2], acc[mt][nt][3],
                                    af[mt][0], af[mt][1], af[mt][2], af[mt][3],
                                    bf[nt][0], bf[nt][1]);
        }

        if (kt + 1 < PKT) CP_WAIT0();
        __syncthreads();
    }

    // Epilogue: fragment (r,2c),(r,2c+1),(r+8,2c),(r+8,2c+1) -> [B,H,L,D]
    #pragma unroll
    for (int mt = 0; mt < 2; mt++) {
        #pragma unroll
        for (int nt = 0; nt < 8; nt++) {
            const int n  = n0 + wn * 64 + nt * 8 + 2 * lc;
            const int h  = n >> 6;
            const int d  = n & 63;
            const int m1 = m0 + wm * 32 + mt * 16 + lr;
            const int b1 = m1 >> 10, l1 = m1 & 1023;
            float2 v01 = make_float2(acc[mt][nt][0], acc[mt][nt][1]);
            *(float2*)&out[(((size_t)(b1 * HH + h) * LL + l1) * DD) + d] = v01;
            const int m2 = m1 + 8;
            const int b2 = m2 >> 10, l2 = m2 & 1023;
            float2 v23 = make_float2(acc[mt][nt][2], acc[mt][nt][3]);
            *(float2*)&out[(((size_t)(b2 * HH + h) * LL + l2) * DD) + d] = v23;
        }
    }
}

// ---------------------------------------------------------------------------
// Flash attention (causal), fp32 — unchanged (333us, validated).
// ---------------------------------------------------------------------------
#define QKV_PAD 65
#define P_PAD   68
#define SMEM_ATTN ((3 * 64 * QKV_PAD + 64 * P_PAD) * (int)sizeof(float))

__global__ __launch_bounds__(256, 3)
void attn_kernel(float* __restrict__ out)
{
    extern __shared__ float smf[];
    float* Qs = smf;
    float* Ks = Qs + 64 * QKV_PAD;
    float* Vs = Ks + 64 * QKV_PAD;
    float* Ps = Vs + 64 * QKV_PAD;

    const int it = blockIdx.x;
    const int bh = blockIdx.y;
    const int b  = bh >> 3;
    const int h  = bh & 7;

    const float* Qb = g_q + (size_t)bh * LL * DD;
    const float* Kb = g_k + (size_t)bh * LL * DD;
    const float* Vb = g_v + (size_t)bh * LL * DD;

    const int tx = threadIdx.x, ty = threadIdx.y;
    const int tid = ty * 16 + tx;
    const float scale = 0.125f;

    for (int idx = tid; idx < 64 * 16; idx += 256) {
        const int r = idx >> 4;
        const int c = (idx & 15) * 4;
        const float4 v = *(const float4*)&Qb[(size_t)(it * 64 + r) * DD + c];
        Qs[r * QKV_PAD + c + 0] = v.x;
        Qs[r * QKV_PAD + c + 1] = v.y;
        Qs[r * QKV_PAD + c + 2] = v.z;
        Qs[r * QKV_PAD + c + 3] = v.w;
    }

    float o[4][4] = {};
    float m_i[4], l_i[4];
    #pragma unroll
    for (int i = 0; i < 4; i++) { m_i[i] = -1e30f; l_i[i] = 0.0f; }

    for (int jt = 0; jt <= it; jt++) {
        __syncthreads();

        for (int idx = tid; idx < 64 * 16; idx += 256) {
            const int r = idx >> 4;
            const int c = (idx & 15) * 4;
            const float4 kv = *(const float4*)&Kb[(size_t)(jt * 64 + r) * DD + c];
            Ks[r * QKV_PAD + c + 0] = kv.x;
            Ks[r * QKV_PAD + c + 1] = kv.y;
            Ks[r * QKV_PAD + c + 2] = kv.z;
            Ks[r * QKV_PAD + c + 3] = kv.w;
            const float4 vv = *(const float4*)&Vb[(size_t)(jt * 64 + r) * DD + c];
            Vs[r * QKV_PAD + c + 0] = vv.x;
            Vs[r * QKV_PAD + c + 1] = vv.y;
            Vs[r * QKV_PAD + c + 2] = vv.z;
            Vs[r * QKV_PAD + c + 3] = vv.w;
        }
        __syncthreads();

        float s[4][4] = {};
        #pragma unroll 8
        for (int dk = 0; dk < 64; dk++) {
            float a[4], bq[4];
            #pragma unroll
            for (int i = 0; i < 4; i++) a[i] = Qs[(ty * 4 + i) * QKV_PAD + dk];
            #pragma unroll
            for (int j = 0; j < 4; j++) bq[j] = Ks[(tx + 16 * j) * QKV_PAD + dk];
            #pragma unroll
            for (int i = 0; i < 4; i++)
                #pragma unroll
                for (int j = 0; j < 4; j++)
                    s[i][j] += a[i] * bq[j];
        }

        #pragma unroll
        for (int i = 0; i < 4; i++) {
            const int qr = it * 64 + ty * 4 + i;
            #pragma unroll
            for (int j = 0; j < 4; j++) {
                const int kc = jt * 64 + tx + 16 * j;
                s[i][j] = (kc > qr) ? -1e30f : s[i][j] * scale;
            }
        }

        #pragma unroll
        for (int i = 0; i < 4; i++) {
            float mx = fmaxf(fmaxf(s[i][0], s[i][1]), fmaxf(s[i][2], s[i][3]));
            #pragma unroll
            for (int off = 1; off < 16; off <<= 1)
                mx = fmaxf(mx, __shfl_xor_sync(0xffffffffu, mx, off));
            const float mnew = fmaxf(m_i[i], mx);
            const float f = __expf(m_i[i] - mnew);
            float rs = 0.0f;
            #pragma unroll
            for (int j = 0; j < 4; j++) {
                const float p = __expf(s[i][j] - mnew);
                Ps[(ty * 4 + i) * P_PAD + tx + 16 * j] = p;
                rs += p;
            }
            #pragma unroll
            for (int off = 1; off < 16; off <<= 1)
                rs += __shfl_xor_sync(0xffffffffu, rs, off);
            l_i[i] = l_i[i] * f + rs;
            m_i[i] = mnew;
            #pragma unroll
            for (int j = 0; j < 4; j++) o[i][j] *= f;
        }
        __syncthreads();

        #pragma unroll 8
        for (int c = 0; c < 64; c++) {
            float p[4], v[4];
            #pragma unroll
            for (int i = 0; i < 4; i++) p[i] = Ps[(ty * 4 + i) * P_PAD + c];
            #pragma unroll
            for (int j = 0; j < 4; j++) v[j] = Vs[c * QKV_PAD + tx + 16 * j];
            #pragma unroll
            for (int i = 0; i < 4; i++)
                #pragma unroll
                for (int j = 0; j < 4; j++)
                    o[i][j] += p[i] * v[j];
        }
    }

    #pragma unroll
    for (int i = 0; i < 4; i++) {
        const int l = it * 64 + ty * 4 + i;
        const float inv = 1.0f / l_i[i];
        float* op = &out[((size_t)(b * LL + l)) * DOUT + h * DD];
        #pragma unroll
        for (int j = 0; j < 4; j++)
            op[tx + 16 * j] = o[i][j] * inv;
    }
}

// ---------------------------------------------------------------------------
extern "C" void kernel_launch(void* const* d_in, const int* in_sizes, int n_in,
                              void* d_out, int out_size)
{
    const float* Qseq = (const float*)d_in[0];
    const float* Kseq = (const float*)d_in[1];
    const float* Vseq = (const float*)d_in[2];
    const float* WQ   = (const float*)d_in[3];
    const float* WK   = (const float*)d_in[4];
    const float* WV   = (const float*)d_in[5];
    float* out = (float*)d_out;

    cudaFuncSetAttribute(proj_mma_kernel,
                         cudaFuncAttributeMaxDynamicSharedMemorySize, SMEM_PROJ);
    cudaFuncSetAttribute(attn_kernel,
                         cudaFuncAttributeMaxDynamicSharedMemorySize, SMEM_ATTN);

    dim3 tblk(32, 8);
    dim3 tgrd(DOUT / 32, DIN / 32, 3);
    transpose_w<<<tgrd, tblk>>>(WQ, WK, WV);

    dim3 pgrd(DOUT / PTN, MM / PTM, 3);   // (4, 64, 3)
    proj_mma_kernel<<<pgrd, 256, SMEM_PROJ>>>(Qseq, Kseq, Vseq);

    dim3 ablk(16, 16);
    dim3 agrd(LL / 64, BB * HH);          // (16, 64)
    attn_kernel<<<agrd, ablk, SMEM_ATTN>>>(out);
}

// round 6
// speedup vs baseline: 2.6174x; 1.7331x over previous
#include <cuda_runtime.h>
#include <cstdint>

// Problem constants
#define BB   8
#define LL   1024
#define DIN  512
#define HH   8
#define DD   64
#define DOUT 512
#define MM   (BB * LL)   // 8192

// Scratch: projected q, k, v in [B, H, L, D] layout (16 MB each)
__device__ float g_q[BB * HH * LL * DD];
__device__ float g_k[BB * HH * LL * DD];
__device__ float g_v[BB * HH * LL * DD];
// Transposed weights: Wt[n][k] = W[k][n], 3 matrices
__device__ float g_wt[3 * DIN * DOUT];

// ===========================================================================
// mma.sync helpers (sm_80+ PTX — valid on sm_103 family target)
// ===========================================================================
__device__ __forceinline__ uint32_t f2tf32(float f) {
    uint32_t r;
    asm("cvt.rna.tf32.f32 %0, %1;" : "=r"(r) : "f"(f));
    return r;
}

__device__ __forceinline__ void mma_tf32_16n8k8(float& d0, float& d1, float& d2, float& d3,
                                                uint32_t a0, uint32_t a1, uint32_t a2, uint32_t a3,
                                                uint32_t b0, uint32_t b1) {
    asm volatile(
        "mma.sync.aligned.m16n8k8.row.col.f32.tf32.tf32.f32 "
        "{%0,%1,%2,%3}, {%4,%5,%6,%7}, {%8,%9}, {%0,%1,%2,%3};"
        : "+f"(d0), "+f"(d1), "+f"(d2), "+f"(d3)
        : "r"(a0), "r"(a1), "r"(a2), "r"(a3), "r"(b0), "r"(b1));
}

__device__ __forceinline__ uint32_t smem_u32(const void* p) {
    uint32_t a;
    asm("{ .reg .u64 t; cvta.to.shared.u64 t, %1; cvt.u32.u64 %0, t; }"
        : "=r"(a) : "l"(p));
    return a;
}

#define CP_ASYNC16(dst_u32, src_ptr) \
    asm volatile("cp.async.cg.shared.global [%0], [%1], 16;" :: "r"(dst_u32), "l"(src_ptr))
#define CP_COMMIT()  asm volatile("cp.async.commit_group;" ::: "memory")
#define CP_WAIT0()   asm volatile("cp.async.wait_group 0;" ::: "memory")

// ===========================================================================
// Weight transpose: Wt[n][k] = W[k][n]
// ===========================================================================
__global__ void transpose_w(const float* __restrict__ Wq,
                            const float* __restrict__ Wk,
                            const float* __restrict__ Wv)
{
    const float* W = (blockIdx.z == 0) ? Wq : (blockIdx.z == 1) ? Wk : Wv;
    float* Wt = g_wt + (size_t)blockIdx.z * DIN * DOUT;

    __shared__ float t[32][33];
    const int tx = threadIdx.x, ty = threadIdx.y;
    int x = blockIdx.x * 32 + tx;
    int y = blockIdx.y * 32 + ty;
    #pragma unroll
    for (int j = 0; j < 32; j += 8)
        t[ty + j][tx] = W[(size_t)(y + j) * DOUT + x];
    __syncthreads();
    x = blockIdx.y * 32 + tx;
    y = blockIdx.x * 32 + ty;
    #pragma unroll
    for (int j = 0; j < 32; j += 8)
        Wt[(size_t)(y + j) * DIN + x] = t[tx][ty + j];
}

// ===========================================================================
// tf32 mma.sync projection (validated round 3): Y = X @ W
// ===========================================================================
#define PTM 128
#define PTN 128
#define PTK 32
#define PPADJ 36
#define PKT  (DIN / PTK)   // 16

#define A_WORDS (PTM * PPADJ)
#define B_WORDS (PTN * PPADJ)
#define SMEM_PROJ ((2 * (A_WORDS + B_WORDS)) * (int)sizeof(float))

__global__ __launch_bounds__(256)
void proj_mma_kernel(const float* __restrict__ Xq, const float* __restrict__ Xk,
                     const float* __restrict__ Xv)
{
    extern __shared__ float sp[];
    float* As[2] = { sp,                sp + A_WORDS };
    float* Bs[2] = { sp + 2 * A_WORDS,  sp + 2 * A_WORDS + B_WORDS };

    const float* X;
    float* out;
    if (blockIdx.z == 0)      { X = Xq; out = g_q; }
    else if (blockIdx.z == 1) { X = Xk; out = g_k; }
    else                      { X = Xv; out = g_v; }
    const float* Wt = g_wt + (size_t)blockIdx.z * DIN * DOUT;

    const int tid  = threadIdx.x;
    const int wid  = tid >> 5;
    const int lane = tid & 31;
    const int wm   = wid & 3;
    const int wn   = wid >> 2;
    const int m0   = blockIdx.y * PTM;
    const int n0   = blockIdx.x * PTN;

    const int lr = lane >> 2;
    const int lc = lane & 3;

    uint32_t a_dst[4], b_dst[4];
    const float* a_src[4];
    const float* b_src[4];
    #pragma unroll
    for (int i = 0; i < 4; i++) {
        const int idx = i * 256 + tid;
        const int r   = idx >> 3;
        const int c4  = idx & 7;
        a_dst[i] = (uint32_t)((r * PPADJ + c4 * 4) * 4);
        b_dst[i] = a_dst[i];
        a_src[i] = &X [(size_t)(m0 + r) * DIN + c4 * 4];
        b_src[i] = &Wt[(size_t)(n0 + r) * DIN + c4 * 4];
    }
    const uint32_t sa[2] = { smem_u32(As[0]), smem_u32(As[1]) };
    const uint32_t sb[2] = { smem_u32(Bs[0]), smem_u32(Bs[1]) };

    float acc[2][8][4];
    #pragma unroll
    for (int mt = 0; mt < 2; mt++)
        #pragma unroll
        for (int nt = 0; nt < 8; nt++)
            #pragma unroll
            for (int q = 0; q < 4; q++) acc[mt][nt][q] = 0.0f;

    #pragma unroll
    for (int i = 0; i < 4; i++) {
        CP_ASYNC16(sa[0] + a_dst[i], a_src[i]);
        CP_ASYNC16(sb[0] + b_dst[i], b_src[i]);
    }
    CP_COMMIT();
    CP_WAIT0();
    __syncthreads();

    for (int kt = 0; kt < PKT; kt++) {
        const int cur = kt & 1;
        if (kt + 1 < PKT) {
            const int nxt = cur ^ 1;
            const int koff = (kt + 1) * PTK;
            #pragma unroll
            for (int i = 0; i < 4; i++) {
                CP_ASYNC16(sa[nxt] + a_dst[i], a_src[i] + koff);
                CP_ASYNC16(sb[nxt] + b_dst[i], b_src[i] + koff);
            }
            CP_COMMIT();
        }

        const float* A = As[cur];
        const float* B = Bs[cur];
        #pragma unroll
        for (int ks = 0; ks < 4; ks++) {
            const int kb = ks * 8;
            uint32_t af[2][4];
            #pragma unroll
            for (int mt = 0; mt < 2; mt++) {
                const int rb = wm * 32 + mt * 16 + lr;
                af[mt][0] = f2tf32(A[ rb      * PPADJ + kb + lc    ]);
                af[mt][1] = f2tf32(A[(rb + 8) * PPADJ + kb + lc    ]);
                af[mt][2] = f2tf32(A[ rb      * PPADJ + kb + lc + 4]);
                af[mt][3] = f2tf32(A[(rb + 8) * PPADJ + kb + lc + 4]);
            }
            uint32_t bf[8][2];
            #pragma unroll
            for (int nt = 0; nt < 8; nt++) {
                const int nb = wn * 64 + nt * 8 + lr;
                bf[nt][0] = f2tf32(B[nb * PPADJ + kb + lc    ]);
                bf[nt][1] = f2tf32(B[nb * PPADJ + kb + lc + 4]);
            }
            #pragma unroll
            for (int mt = 0; mt < 2; mt++)
                #pragma unroll
                for (int nt = 0; nt < 8; nt++)
                    mma_tf32_16n8k8(acc[mt][nt][0], acc[mt][nt][1],
                                    acc[mt][nt][2], acc[mt][nt][3],
                                    af[mt][0], af[mt][1], af[mt][2], af[mt][3],
                                    bf[nt][0], bf[nt][1]);
        }

        if (kt + 1 < PKT) CP_WAIT0();
        __syncthreads();
    }

    #pragma unroll
    for (int mt = 0; mt < 2; mt++) {
        #pragma unroll
        for (int nt = 0; nt < 8; nt++) {
            const int n  = n0 + wn * 64 + nt * 8 + 2 * lc;
            const int h  = n >> 6;
            const int d  = n & 63;
            const int m1 = m0 + wm * 32 + mt * 16 + lr;
            const int b1 = m1 >> 10, l1 = m1 & 1023;
            float2 v01 = make_float2(acc[mt][nt][0], acc[mt][nt][1]);
            *(float2*)&out[(((size_t)(b1 * HH + h) * LL + l1) * DD) + d] = v01;
            const int m2 = m1 + 8;
            const int b2 = m2 >> 10, l2 = m2 & 1023;
            float2 v23 = make_float2(acc[mt][nt][2], acc[mt][nt][3]);
            *(float2*)&out[(((size_t)(b2 * HH + h) * LL + l2) * DD) + d] = v23;
        }
    }
}

// ===========================================================================
// Flash attention with tf32 mma.sync.
// CTA = (bh, 128-q tile); 8 warps x 16 q-rows. Key tiles of 64.
// S = Q K^T  (K d-major in smem);  O += P V  (V stored transposed: Vt[d][kc]).
// Q fragments cached in registers; Q smem region reused as P buffer
// (warp-private rows -> only __syncwarp between softmax and PV).
// Softmax scale folded into Q smem store.
// ===========================================================================
#define AQT   128
#define AKT   64
#define KPAD  68
#define VPAD  69
#define PPAD  68
#define SMEM_ATTN ((AKT * KPAD + AKT * VPAD + AQT * PPAD) * (int)sizeof(float))

__global__ __launch_bounds__(256, 2)
void attn_mma_kernel(float* __restrict__ out)
{
    extern __shared__ float smf[];
    float* Ks = smf;                    // [64][KPAD]  (kc-major, d cols)
    float* Vt = Ks + AKT * KPAD;        // [64][VPAD]  (d-major, kc cols)
    float* QP = Vt + AKT * VPAD;        // [128][PPAD] Q (scaled), then P

    const int it = (int)gridDim.x - 1 - (int)blockIdx.x;   // heavy tiles first
    const int bh = blockIdx.y;
    const int b  = bh >> 3;
    const int h  = bh & 7;

    const float* Qb = g_q + (size_t)bh * LL * DD;
    const float* Kb = g_k + (size_t)bh * LL * DD;
    const float* Vb = g_v + (size_t)bh * LL * DD;

    const int tid  = threadIdx.x;
    const int wid  = tid >> 5;
    const int lane = tid & 31;
    const int lr   = lane >> 2;     // 0..7
    const int lc   = lane & 3;      // 0..3
    const int q0   = it * AQT;
    const int wq   = wid * 16;      // warp's q offset within tile

    // ---- Load Q tile (scaled) into QP ----
    #pragma unroll
    for (int i = 0; i < 8; i++) {
        const int idx = i * 256 + tid;
        const int r = idx >> 4;
        const int c = (idx & 15) * 4;
        float4 v = *(const float4*)&Qb[(size_t)(q0 + r) * DD + c];
        QP[r * PPAD + c + 0] = v.x * 0.125f;
        QP[r * PPAD + c + 1] = v.y * 0.125f;
        QP[r * PPAD + c + 2] = v.z * 0.125f;
        QP[r * PPAD + c + 3] = v.w * 0.125f;
    }
    __syncthreads();

    // ---- Build Q fragments (held in registers for all key tiles) ----
    uint32_t qf[8][4];
    #pragma unroll
    for (int kk = 0; kk < 8; kk++) {
        const int row = wq + lr;
        qf[kk][0] = f2tf32(QP[ row      * PPAD + kk * 8 + lc    ]);
        qf[kk][1] = f2tf32(QP[(row + 8) * PPAD + kk * 8 + lc    ]);
        qf[kk][2] = f2tf32(QP[ row      * PPAD + kk * 8 + lc + 4]);
        qf[kk][3] = f2tf32(QP[(row + 8) * PPAD + kk * 8 + lc + 4]);
    }
    __syncthreads();   // everyone done reading Q before QP becomes P

    float oa[8][4];
    #pragma unroll
    for (int nt = 0; nt < 8; nt++)
        #pragma unroll
        for (int q = 0; q < 4; q++) oa[nt][q] = 0.0f;
    float m0v = -1e30f, m1v = -1e30f, l0 = 0.0f, l1 = 0.0f;

    const int jmax = 2 * it + 1;
    for (int jt = 0; jt <= jmax; jt++) {
        __syncthreads();   // prior iteration done reading Ks/Vt

        // ---- Load K tile (direct) and V tile (transposed) ----
        #pragma unroll
        for (int i = 0; i < 4; i++) {
            const int idx = i * 256 + tid;
            const int kc  = idx >> 4;
            const int c   = (idx & 15) * 4;
            float4 kv = *(const float4*)&Kb[(size_t)(jt * AKT + kc) * DD + c];
            *(float4*)&Ks[kc * KPAD + c] = kv;
            float4 vv = *(const float4*)&Vb[(size_t)(jt * AKT + kc) * DD + c];
            Vt[(c + 0) * VPAD + kc] = vv.x;
            Vt[(c + 1) * VPAD + kc] = vv.y;
            Vt[(c + 2) * VPAD + kc] = vv.z;
            Vt[(c + 3) * VPAD + kc] = vv.w;
        }
        __syncthreads();

        // ---- S = Q K^T ----
        float sa[8][4];
        #pragma unroll
        for (int nt = 0; nt < 8; nt++)
            #pragma unroll
            for (int q = 0; q < 4; q++) sa[nt][q] = 0.0f;

        #pragma unroll
        for (int kk = 0; kk < 8; kk++) {
            uint32_t bf[8][2];
            #pragma unroll
            for (int nt = 0; nt < 8; nt++) {
                const int nb = nt * 8 + lr;
                bf[nt][0] = f2tf32(Ks[nb * KPAD + kk * 8 + lc    ]);
                bf[nt][1] = f2tf32(Ks[nb * KPAD + kk * 8 + lc + 4]);
            }
            #pragma unroll
            for (int nt = 0; nt < 8; nt++)
                mma_tf32_16n8k8(sa[nt][0], sa[nt][1], sa[nt][2], sa[nt][3],
                                qf[kk][0], qf[kk][1], qf[kk][2], qf[kk][3],
                                bf[nt][0], bf[nt][1]);
        }

        // ---- Causal mask (only tiles crossing the diagonal for this warp) ----
        const int qg0 = q0 + wq + lr;
        const int qg1 = qg0 + 8;
        if (jt * AKT + AKT - 1 > q0 + wq) {
            #pragma unroll
            for (int nt = 0; nt < 8; nt++) {
                const int kc0 = jt * AKT + nt * 8 + 2 * lc;
                if (kc0     > qg0) sa[nt][0] = -1e30f;
                if (kc0 + 1 > qg0) sa[nt][1] = -1e30f;
                if (kc0     > qg1) sa[nt][2] = -1e30f;
                if (kc0 + 1 > qg1) sa[nt][3] = -1e30f;
            }
        }

        // ---- Online softmax on fragments ----
        float tmax0 = -1e30f, tmax1 = -1e30f;
        #pragma unroll
        for (int nt = 0; nt < 8; nt++) {
            tmax0 = fmaxf(tmax0, fmaxf(sa[nt][0], sa[nt][1]));
            tmax1 = fmaxf(tmax1, fmaxf(sa[nt][2], sa[nt][3]));
        }
        tmax0 = fmaxf(tmax0, __shfl_xor_sync(0xffffffffu, tmax0, 1));
        tmax0 = fmaxf(tmax0, __shfl_xor_sync(0xffffffffu, tmax0, 2));
        tmax1 = fmaxf(tmax1, __shfl_xor_sync(0xffffffffu, tmax1, 1));
        tmax1 = fmaxf(tmax1, __shfl_xor_sync(0xffffffffu, tmax1, 2));

        const float mn0 = fmaxf(m0v, tmax0);
        const float mn1 = fmaxf(m1v, tmax1);
        const float f0  = __expf(m0v - mn0);
        const float f1  = __expf(m1v - mn1);

        float rs0 = 0.0f, rs1 = 0.0f;
        #pragma unroll
        for (int nt = 0; nt < 8; nt++) {
            const float p00 = __expf(sa[nt][0] - mn0);
            const float p01 = __expf(sa[nt][1] - mn0);
            const float p10 = __expf(sa[nt][2] - mn1);
            const float p11 = __expf(sa[nt][3] - mn1);
            rs0 += p00 + p01;
            rs1 += p10 + p11;
            *(float2*)&QP[(wq + lr    ) * PPAD + nt * 8 + 2 * lc] = make_float2(p00, p01);
            *(float2*)&QP[(wq + lr + 8) * PPAD + nt * 8 + 2 * lc] = make_float2(p10, p11);
        }
        rs0 += __shfl_xor_sync(0xffffffffu, rs0, 1);
        rs0 += __shfl_xor_sync(0xffffffffu, rs0, 2);
        rs1 += __shfl_xor_sync(0xffffffffu, rs1, 1);
        rs1 += __shfl_xor_sync(0xffffffffu, rs1, 2);

        l0 = l0 * f0 + rs0;  m0v = mn0;
        l1 = l1 * f1 + rs1;  m1v = mn1;
        #pragma unroll
        for (int nt = 0; nt < 8; nt++) {
            oa[nt][0] *= f0;  oa[nt][1] *= f0;
            oa[nt][2] *= f1;  oa[nt][3] *= f1;
        }
        __syncwarp();

        // ---- O += P V (A-frags from warp-private P rows, B from Vt) ----
        #pragma unroll
        for (int kk = 0; kk < 8; kk++) {
            uint32_t pf[4];
            pf[0] = f2tf32(QP[(wq + lr    ) * PPAD + kk * 8 + lc    ]);
            pf[1] = f2tf32(QP[(wq + lr + 8) * PPAD + kk * 8 + lc    ]);
            pf[2] = f2tf32(QP[(wq + lr    ) * PPAD + kk * 8 + lc + 4]);
            pf[3] = f2tf32(QP[(wq + lr + 8) * PPAD + kk * 8 + lc + 4]);
            uint32_t vf[8][2];
            #pragma unroll
            for (int nt = 0; nt < 8; nt++) {
                const int nb = nt * 8 + lr;
                vf[nt][0] = f2tf32(Vt[nb * VPAD + kk * 8 + lc    ]);
                vf[nt][1] = f2tf32(Vt[nb * VPAD + kk * 8 + lc + 4]);
            }
            #pragma unroll
            for (int nt = 0; nt < 8; nt++)
                mma_tf32_16n8k8(oa[nt][0], oa[nt][1], oa[nt][2], oa[nt][3],
                                pf[0], pf[1], pf[2], pf[3],
                                vf[nt][0], vf[nt][1]);
        }
        __syncwarp();
    }

    // ---- Epilogue: normalize and store to out[b, l, h*64 + d] ----
    const float inv0 = 1.0f / l0;
    const float inv1 = 1.0f / l1;
    const int q1 = q0 + wq + lr;
    const int q2 = q1 + 8;
    #pragma unroll
    for (int nt = 0; nt < 8; nt++) {
        const int d = nt * 8 + 2 * lc;
        *(float2*)&out[((size_t)(b * LL + q1)) * DOUT + h * DD + d] =
            make_float2(oa[nt][0] * inv0, oa[nt][1] * inv0);
        *(float2*)&out[((size_t)(b * LL + q2)) * DOUT + h * DD + d] =
            make_float2(oa[nt][2] * inv1, oa[nt][3] * inv1);
    }
}

// ---------------------------------------------------------------------------
extern "C" void kernel_launch(void* const* d_in, const int* in_sizes, int n_in,
                              void* d_out, int out_size)
{
    const float* Qseq = (const float*)d_in[0];
    const float* Kseq = (const float*)d_in[1];
    const float* Vseq = (const float*)d_in[2];
    const float* WQ   = (const float*)d_in[3];
    const float* WK   = (const float*)d_in[4];
    const float* WV   = (const float*)d_in[5];
    float* out = (float*)d_out;

    cudaFuncSetAttribute(proj_mma_kernel,
                         cudaFuncAttributeMaxDynamicSharedMemorySize, SMEM_PROJ);
    cudaFuncSetAttribute(attn_mma_kernel,
                         cudaFuncAttributeMaxDynamicSharedMemorySize, SMEM_ATTN);

    dim3 tblk(32, 8);
    dim3 tgrd(DOUT / 32, DIN / 32, 3);
    transpose_w<<<tgrd, tblk>>>(WQ, WK, WV);

    dim3 pgrd(DOUT / PTN, MM / PTM, 3);   // (4, 64, 3)
    proj_mma_kernel<<<pgrd, 256, SMEM_PROJ>>>(Qseq, Kseq, Vseq);

    dim3 agrd(LL / AQT, BB * HH);         // (8, 64)
    attn_mma_kernel<<<agrd, 256, SMEM_ATTN>>>(out);
}

// round 7
// speedup vs baseline: 2.8583x; 1.0920x over previous
#include <cuda_runtime.h>
#include <cstdint>

// Problem constants
#define BB   8
#define LL   1024
#define DIN  512
#define HH   8
#define DD   64
#define DOUT 512
#define MM   (BB * LL)   // 8192

// Scratch: projected q, k, v in [B, H, L, D] layout, tf32-pre-rounded
__device__ float g_q[BB * HH * LL * DD];
__device__ float g_k[BB * HH * LL * DD];
__device__ float g_v[BB * HH * LL * DD];
// Transposed weights: Wt[n][k] = W[k][n], tf32-pre-rounded, 3 matrices
__device__ float g_wt[3 * DIN * DOUT];

// ===========================================================================
// mma.sync helpers (sm_80+ PTX — valid on sm_103 family target)
// ===========================================================================
__device__ __forceinline__ uint32_t f2tf32(float f) {
    uint32_t r;
    asm("cvt.rna.tf32.f32 %0, %1;" : "=r"(r) : "f"(f));
    return r;
}

__device__ __forceinline__ float ex2f(float x) {
    float y;
    asm("ex2.approx.ftz.f32 %0, %1;" : "=f"(y) : "f"(x));
    return y;
}

__device__ __forceinline__ void mma_tf32_16n8k8(float& d0, float& d1, float& d2, float& d3,
                                                uint32_t a0, uint32_t a1, uint32_t a2, uint32_t a3,
                                                uint32_t b0, uint32_t b1) {
    asm volatile(
        "mma.sync.aligned.m16n8k8.row.col.f32.tf32.tf32.f32 "
        "{%0,%1,%2,%3}, {%4,%5,%6,%7}, {%8,%9}, {%0,%1,%2,%3};"
        : "+f"(d0), "+f"(d1), "+f"(d2), "+f"(d3)
        : "r"(a0), "r"(a1), "r"(a2), "r"(a3), "r"(b0), "r"(b1));
}

__device__ __forceinline__ uint32_t smem_u32(const void* p) {
    uint32_t a;
    asm("{ .reg .u64 t; cvta.to.shared.u64 t, %1; cvt.u32.u64 %0, t; }"
        : "=r"(a) : "l"(p));
    return a;
}

#define CP_ASYNC16(dst_u32, src_ptr) \
    asm volatile("cp.async.cg.shared.global [%0], [%1], 16;" :: "r"(dst_u32), "l"(src_ptr))
#define CP_COMMIT()  asm volatile("cp.async.commit_group;" ::: "memory")
#define CP_WAIT0()   asm volatile("cp.async.wait_group 0;" ::: "memory")
#define CP_WAIT1()   asm volatile("cp.async.wait_group 1;" ::: "memory")

// ===========================================================================
// Weight transpose + tf32 pre-round: Wt[n][k] = tf32(W[k][n])
// ===========================================================================
__global__ void transpose_w(const float* __restrict__ Wq,
                            const float* __restrict__ Wk,
                            const float* __restrict__ Wv)
{
    const float* W = (blockIdx.z == 0) ? Wq : (blockIdx.z == 1) ? Wk : Wv;
    float* Wt = g_wt + (size_t)blockIdx.z * DIN * DOUT;

    __shared__ float t[32][33];
    const int tx = threadIdx.x, ty = threadIdx.y;
    int x = blockIdx.x * 32 + tx;
    int y = blockIdx.y * 32 + ty;
    #pragma unroll
    for (int j = 0; j < 32; j += 8)
        t[ty + j][tx] = W[(size_t)(y + j) * DOUT + x];
    __syncthreads();
    x = blockIdx.y * 32 + tx;
    y = blockIdx.x * 32 + ty;
    #pragma unroll
    for (int j = 0; j < 32; j += 8)
        Wt[(size_t)(y + j) * DIN + x] = __uint_as_float(f2tf32(t[tx][ty + j]));
}

// ===========================================================================
// tf32 mma.sync projection: Y = X @ W.  B (weights) pre-rounded -> raw bits.
// Epilogue stores tf32-rounded results (so attention can use raw bits).
// ===========================================================================
#define PTM 128
#define PTN 128
#define PTK 32
#define PPADJ 36
#define PKT  (DIN / PTK)   // 16

#define A_WORDS (PTM * PPADJ)
#define B_WORDS (PTN * PPADJ)
#define SMEM_PROJ ((2 * (A_WORDS + B_WORDS)) * (int)sizeof(float))

__global__ __launch_bounds__(256)
void proj_mma_kernel(const float* __restrict__ Xq, const float* __restrict__ Xk,
                     const float* __restrict__ Xv)
{
    extern __shared__ float sp[];
    float* As[2] = { sp,                sp + A_WORDS };
    float* Bs[2] = { sp + 2 * A_WORDS,  sp + 2 * A_WORDS + B_WORDS };

    const float* X;
    float* out;
    if (blockIdx.z == 0)      { X = Xq; out = g_q; }
    else if (blockIdx.z == 1) { X = Xk; out = g_k; }
    else                      { X = Xv; out = g_v; }
    const float* Wt = g_wt + (size_t)blockIdx.z * DIN * DOUT;

    const int tid  = threadIdx.x;
    const int wid  = tid >> 5;
    const int lane = tid & 31;
    const int wm   = wid & 3;
    const int wn   = wid >> 2;
    const int m0   = blockIdx.y * PTM;
    const int n0   = blockIdx.x * PTN;

    const int lr = lane >> 2;
    const int lc = lane & 3;

    uint32_t a_dst[4], b_dst[4];
    const float* a_src[4];
    const float* b_src[4];
    #pragma unroll
    for (int i = 0; i < 4; i++) {
        const int idx = i * 256 + tid;
        const int r   = idx >> 3;
        const int c4  = idx & 7;
        a_dst[i] = (uint32_t)((r * PPADJ + c4 * 4) * 4);
        b_dst[i] = a_dst[i];
        a_src[i] = &X [(size_t)(m0 + r) * DIN + c4 * 4];
        b_src[i] = &Wt[(size_t)(n0 + r) * DIN + c4 * 4];
    }
    const uint32_t sa[2] = { smem_u32(As[0]), smem_u32(As[1]) };
    const uint32_t sb[2] = { smem_u32(Bs[0]), smem_u32(Bs[1]) };

    float acc[2][8][4];
    #pragma unroll
    for (int mt = 0; mt < 2; mt++)
        #pragma unroll
        for (int nt = 0; nt < 8; nt++)
            #pragma unroll
            for (int q = 0; q < 4; q++) acc[mt][nt][q] = 0.0f;

    #pragma unroll
    for (int i = 0; i < 4; i++) {
        CP_ASYNC16(sa[0] + a_dst[i], a_src[i]);
        CP_ASYNC16(sb[0] + b_dst[i], b_src[i]);
    }
    CP_COMMIT();
    CP_WAIT0();
    __syncthreads();

    for (int kt = 0; kt < PKT; kt++) {
        const int cur = kt & 1;
        if (kt + 1 < PKT) {
            const int nxt = cur ^ 1;
            const int koff = (kt + 1) * PTK;
            #pragma unroll
            for (int i = 0; i < 4; i++) {
                CP_ASYNC16(sa[nxt] + a_dst[i], a_src[i] + koff);
                CP_ASYNC16(sb[nxt] + b_dst[i], b_src[i] + koff);
            }
            CP_COMMIT();
        }

        const float* A = As[cur];
        const float* B = Bs[cur];
        #pragma unroll
        for (int ks = 0; ks < 4; ks++) {
            const int kb = ks * 8;
            uint32_t af[2][4];
            #pragma unroll
            for (int mt = 0; mt < 2; mt++) {
                const int rb = wm * 32 + mt * 16 + lr;
                af[mt][0] = f2tf32(A[ rb      * PPADJ + kb + lc    ]);
                af[mt][1] = f2tf32(A[(rb + 8) * PPADJ + kb + lc    ]);
                af[mt][2] = f2tf32(A[ rb      * PPADJ + kb + lc + 4]);
                af[mt][3] = f2tf32(A[(rb + 8) * PPADJ + kb + lc + 4]);
            }
            uint32_t bf[8][2];
            #pragma unroll
            for (int nt = 0; nt < 8; nt++) {
                const int nb = wn * 64 + nt * 8 + lr;
                bf[nt][0] = __float_as_uint(B[nb * PPADJ + kb + lc    ]);  // pre-rounded
                bf[nt][1] = __float_as_uint(B[nb * PPADJ + kb + lc + 4]);
            }
            #pragma unroll
            for (int mt = 0; mt < 2; mt++)
                #pragma unroll
                for (int nt = 0; nt < 8; nt++)
                    mma_tf32_16n8k8(acc[mt][nt][0], acc[mt][nt][1],
                                    acc[mt][nt][2], acc[mt][nt][3],
                                    af[mt][0], af[mt][1], af[mt][2], af[mt][3],
                                    bf[nt][0], bf[nt][1]);
        }

        if (kt + 1 < PKT) CP_WAIT0();
        __syncthreads();
    }

    // Epilogue: store tf32-pre-rounded results into [B,H,L,D]
    #pragma unroll
    for (int mt = 0; mt < 2; mt++) {
        #pragma unroll
        for (int nt = 0; nt < 8; nt++) {
            const int n  = n0 + wn * 64 + nt * 8 + 2 * lc;
            const int h  = n >> 6;
            const int d  = n & 63;
            const int m1 = m0 + wm * 32 + mt * 16 + lr;
            const int b1 = m1 >> 10, l1 = m1 & 1023;
            float2 v01 = make_float2(__uint_as_float(f2tf32(acc[mt][nt][0])),
                                     __uint_as_float(f2tf32(acc[mt][nt][1])));
            *(float2*)&out[(((size_t)(b1 * HH + h) * LL + l1) * DD) + d] = v01;
            const int m2 = m1 + 8;
            const int b2 = m2 >> 10, l2 = m2 & 1023;
            float2 v23 = make_float2(__uint_as_float(f2tf32(acc[mt][nt][2])),
                                     __uint_as_float(f2tf32(acc[mt][nt][3])));
            *(float2*)&out[(((size_t)(b2 * HH + h) * LL + l2) * DD) + d] = v23;
        }
    }
}

// ===========================================================================
// Flash attention, tf32 mma.sync, cp.async double-buffered K/V.
// CTA = (bh, 128-q tile); 8 warps x 16 q-rows; key tiles of 64.
// K: [kc][d] pad 68 (S-phase B-frag conflict-free).
// V: [kc][d] pad 72 (PV-phase B-frag bank = lc*8+lr, conflict-free; no transpose
//    -> cp.async for both K and V).
// K/V fragments use raw bits (g_k/g_v pre-rounded by proj). P uses cvt.rna.
// exp via ex2 (log2e folded into Q scale).
// ===========================================================================
#define AQT   128
#define AKT   64
#define KPAD  68
#define VPAD  72
#define PPAD  68
#define KW    (AKT * KPAD)
#define VW    (AKT * VPAD)
#define SMEM_ATTN ((2 * KW + 2 * VW + AQT * PPAD) * (int)sizeof(float))  // 106496 B

__global__ __launch_bounds__(256, 2)
void attn_mma_kernel(float* __restrict__ out)
{
    extern __shared__ float smf[];
    float* Ksb[2] = { smf,           smf + KW };
    float* Vsb[2] = { smf + 2 * KW,  smf + 2 * KW + VW };
    float* QP     = smf + 2 * KW + 2 * VW;       // [128][PPAD] Q then P

    const int it = (int)gridDim.x - 1 - (int)blockIdx.x;   // heavy tiles first
    const int bh = blockIdx.y;
    const int b  = bh >> 3;
    const int h  = bh & 7;

    const float* Qb = g_q + (size_t)bh * LL * DD;
    const float* Kb = g_k + (size_t)bh * LL * DD;
    const float* Vb = g_v + (size_t)bh * LL * DD;

    const int tid  = threadIdx.x;
    const int wid  = tid >> 5;
    const int lane = tid & 31;
    const int lr   = lane >> 2;     // 0..7
    const int lc   = lane & 3;      // 0..3
    const int q0   = it * AQT;
    const int wq   = wid * 16;

    // Per-thread cp.async slots for K/V tiles (4 x 16B each)
    uint32_t k_dst[4], v_dst[4];
    int      kv_row[4];
    #pragma unroll
    for (int i = 0; i < 4; i++) {
        const int idx = i * 256 + tid;
        const int kc  = idx >> 4;
        const int c   = (idx & 15) * 4;
        k_dst[i] = (uint32_t)((kc * KPAD + c) * 4);
        v_dst[i] = (uint32_t)((kc * VPAD + c) * 4);
        kv_row[i] = kc;
    }
    const uint32_t sk[2] = { smem_u32(Ksb[0]), smem_u32(Ksb[1]) };
    const uint32_t sv[2] = { smem_u32(Vsb[0]), smem_u32(Vsb[1]) };

    // Prologue: issue loads for key tile 0
    {
        #pragma unroll
        for (int i = 0; i < 4; i++) {
            const int c = ((i * 256 + tid) & 15) * 4;
            CP_ASYNC16(sk[0] + k_dst[i], &Kb[(size_t)kv_row[i] * DD + c]);
            CP_ASYNC16(sv[0] + v_dst[i], &Vb[(size_t)kv_row[i] * DD + c]);
        }
        CP_COMMIT();
    }

    // ---- Load Q tile (scaled by 0.125*log2e) into QP ----
    const float QSCALE = 0.125f * 1.4426950408889634f;
    #pragma unroll
    for (int i = 0; i < 8; i++) {
        const int idx = i * 256 + tid;
        const int r = idx >> 4;
        const int c = (idx & 15) * 4;
        float4 v = *(const float4*)&Qb[(size_t)(q0 + r) * DD + c];
        QP[r * PPAD + c + 0] = v.x * QSCALE;
        QP[r * PPAD + c + 1] = v.y * QSCALE;
        QP[r * PPAD + c + 2] = v.z * QSCALE;
        QP[r * PPAD + c + 3] = v.w * QSCALE;
    }
    __syncthreads();

    // ---- Build Q fragments (registers, once) ----
    uint32_t qf[8][4];
    #pragma unroll
    for (int kk = 0; kk < 8; kk++) {
        const int row = wq + lr;
        qf[kk][0] = f2tf32(QP[ row      * PPAD + kk * 8 + lc    ]);
        qf[kk][1] = f2tf32(QP[(row + 8) * PPAD + kk * 8 + lc    ]);
        qf[kk][2] = f2tf32(QP[ row      * PPAD + kk * 8 + lc + 4]);
        qf[kk][3] = f2tf32(QP[(row + 8) * PPAD + kk * 8 + lc + 4]);
    }
    __syncthreads();   // QP now becomes the P buffer

    float oa[8][4];
    #pragma unroll
    for (int nt = 0; nt < 8; nt++)
        #pragma unroll
        for (int q = 0; q < 4; q++) oa[nt][q] = 0.0f;
    float m0v = -1e30f, m1v = -1e30f, l0 = 0.0f, l1 = 0.0f;

    const int jmax = 2 * it + 1;
    for (int jt = 0; jt <= jmax; jt++) {
        const int cur = jt & 1;

        // Prefetch next key tile into the other buffer
        if (jt < jmax) {
            const int nxt = cur ^ 1;
            const size_t base = (size_t)(jt + 1) * AKT;
            #pragma unroll
            for (int i = 0; i < 4; i++) {
                const int c = ((i * 256 + tid) & 15) * 4;
                CP_ASYNC16(sk[nxt] + k_dst[i], &Kb[(base + kv_row[i]) * DD + c]);
                CP_ASYNC16(sv[nxt] + v_dst[i], &Vb[(base + kv_row[i]) * DD + c]);
            }
            CP_COMMIT();
            CP_WAIT1();
        } else {
            CP_WAIT0();
        }
        __syncthreads();

        const float* Ks = Ksb[cur];
        const float* Vs = Vsb[cur];

        // ---- S = Q K^T  (K raw bits: pre-rounded tf32) ----
        float sa2[8][4];
        #pragma unroll
        for (int nt = 0; nt < 8; nt++)
            #pragma unroll
            for (int q = 0; q < 4; q++) sa2[nt][q] = 0.0f;

        #pragma unroll
        for (int kk = 0; kk < 8; kk++) {
            uint32_t bf[8][2];
            #pragma unroll
            for (int nt = 0; nt < 8; nt++) {
                const int nb = nt * 8 + lr;
                bf[nt][0] = __float_as_uint(Ks[nb * KPAD + kk * 8 + lc    ]);
                bf[nt][1] = __float_as_uint(Ks[nb * KPAD + kk * 8 + lc + 4]);
            }
            #pragma unroll
            for (int nt = 0; nt < 8; nt++)
                mma_tf32_16n8k8(sa2[nt][0], sa2[nt][1], sa2[nt][2], sa2[nt][3],
                                qf[kk][0], qf[kk][1], qf[kk][2], qf[kk][3],
                                bf[nt][0], bf[nt][1]);
        }

        // ---- Causal mask ----
        const int qg0 = q0 + wq + lr;
        const int qg1 = qg0 + 8;
        if (jt * AKT + AKT - 1 > q0 + wq) {
            #pragma unroll
            for (int nt = 0; nt < 8; nt++) {
                const int kc0 = jt * AKT + nt * 8 + 2 * lc;
                if (kc0     > qg0) sa2[nt][0] = -1e30f;
                if (kc0 + 1 > qg0) sa2[nt][1] = -1e30f;
                if (kc0     > qg1) sa2[nt][2] = -1e30f;
                if (kc0 + 1 > qg1) sa2[nt][3] = -1e30f;
            }
        }

        // ---- Online softmax (log2 domain) ----
        float tmax0 = -1e30f, tmax1 = -1e30f;
        #pragma unroll
        for (int nt = 0; nt < 8; nt++) {
            tmax0 = fmaxf(tmax0, fmaxf(sa2[nt][0], sa2[nt][1]));
            tmax1 = fmaxf(tmax1, fmaxf(sa2[nt][2], sa2[nt][3]));
        }
        tmax0 = fmaxf(tmax0, __shfl_xor_sync(0xffffffffu, tmax0, 1));
        tmax0 = fmaxf(tmax0, __shfl_xor_sync(0xffffffffu, tmax0, 2));
        tmax1 = fmaxf(tmax1, __shfl_xor_sync(0xffffffffu, tmax1, 1));
        tmax1 = fmaxf(tmax1, __shfl_xor_sync(0xffffffffu, tmax1, 2));

        const float mn0 = fmaxf(m0v, tmax0);
        const float mn1 = fmaxf(m1v, tmax1);
        const float f0  = ex2f(m0v - mn0);
        const float f1  = ex2f(m1v - mn1);

        float rs0 = 0.0f, rs1 = 0.0f;
        #pragma unroll
        for (int nt = 0; nt < 8; nt++) {
            const float p00 = ex2f(sa2[nt][0] - mn0);
            const float p01 = ex2f(sa2[nt][1] - mn0);
            const float p10 = ex2f(sa2[nt][2] - mn1);
            const float p11 = ex2f(sa2[nt][3] - mn1);
            rs0 += p00 + p01;
            rs1 += p10 + p11;
            *(float2*)&QP[(wq + lr    ) * PPAD + nt * 8 + 2 * lc] = make_float2(p00, p01);
            *(float2*)&QP[(wq + lr + 8) * PPAD + nt * 8 + 2 * lc] = make_float2(p10, p11);
        }
        rs0 += __shfl_xor_sync(0xffffffffu, rs0, 1);
        rs0 += __shfl_xor_sync(0xffffffffu, rs0, 2);
        rs1 += __shfl_xor_sync(0xffffffffu, rs1, 1);
        rs1 += __shfl_xor_sync(0xffffffffu, rs1, 2);

        l0 = l0 * f0 + rs0;  m0v = mn0;
        l1 = l1 * f1 + rs1;  m1v = mn1;
        #pragma unroll
        for (int nt = 0; nt < 8; nt++) {
            oa[nt][0] *= f0;  oa[nt][1] *= f0;
            oa[nt][2] *= f1;  oa[nt][3] *= f1;
        }
        __syncwarp();

        // ---- O += P V  (V natural layout [kc][d], raw bits; B(k,n)=Vs[k][n]) ----
        #pragma unroll
        for (int kk = 0; kk < 8; kk++) {
            uint32_t pf[4];
            pf[0] = f2tf32(QP[(wq + lr    ) * PPAD + kk * 8 + lc    ]);
            pf[1] = f2tf32(QP[(wq + lr + 8) * PPAD + kk * 8 + lc    ]);
            pf[2] = f2tf32(QP[(wq + lr    ) * PPAD + kk * 8 + lc + 4]);
            pf[3] = f2tf32(QP[(wq + lr + 8) * PPAD + kk * 8 + lc + 4]);
            uint32_t vf[8][2];
            #pragma unroll
            for (int nt = 0; nt < 8; nt++) {
                vf[nt][0] = __float_as_uint(Vs[(kk * 8 + lc    ) * VPAD + nt * 8 + lr]);
                vf[nt][1] = __float_as_uint(Vs[(kk * 8 + lc + 4) * VPAD + nt * 8 + lr]);
            }
            #pragma unroll
            for (int nt = 0; nt < 8; nt++)
                mma_tf32_16n8k8(oa[nt][0], oa[nt][1], oa[nt][2], oa[nt][3],
                                pf[0], pf[1], pf[2], pf[3],
                                vf[nt][0], vf[nt][1]);
        }
        __syncthreads();   // all warps done with cur K/V + P before next overwrite
    }

    // ---- Epilogue ----
    const float inv0 = 1.0f / l0;
    const float inv1 = 1.0f / l1;
    const int q1 = q0 + wq + lr;
    const int q2 = q1 + 8;
    #pragma unroll
    for (int nt = 0; nt < 8; nt++) {
        const int d = nt * 8 + 2 * lc;
        *(float2*)&out[((size_t)(b * LL + q1)) * DOUT + h * DD + d] =
            make_float2(oa[nt][0] * inv0, oa[nt][1] * inv0);
        *(float2*)&out[((size_t)(b * LL + q2)) * DOUT + h * DD + d] =
            make_float2(oa[nt][2] * inv1, oa[nt][3] * inv1);
    }
}

// ---------------------------------------------------------------------------
extern "C" void kernel_launch(void* const* d_in, const int* in_sizes, int n_in,
                              void* d_out, int out_size)
{
    const float* Qseq = (const float*)d_in[0];
    const float* Kseq = (const float*)d_in[1];
    const float* Vseq = (const float*)d_in[2];
    const float* WQ   = (const float*)d_in[3];
    const float* WK   = (const float*)d_in[4];
    const float* WV   = (const float*)d_in[5];
    float* out = (float*)d_out;

    cudaFuncSetAttribute(proj_mma_kernel,
                         cudaFuncAttributeMaxDynamicSharedMemorySize, SMEM_PROJ);
    cudaFuncSetAttribute(attn_mma_kernel,
                         cudaFuncAttributeMaxDynamicSharedMemorySize, SMEM_ATTN);

    dim3 tblk(32, 8);
    dim3 tgrd(DOUT / 32, DIN / 32, 3);
    transpose_w<<<tgrd, tblk>>>(WQ, WK, WV);

    dim3 pgrd(DOUT / PTN, MM / PTM, 3);   // (4, 64, 3)
    proj_mma_kernel<<<pgrd, 256, SMEM_PROJ>>>(Qseq, Kseq, Vseq);

    dim3 agrd(LL / AQT, BB * HH);         // (8, 64)
    attn_mma_kernel<<<agrd, 256, SMEM_ATTN>>>(out);
}

// round 8
// speedup vs baseline: 4.7409x; 1.6587x over previous
#include <cuda_runtime.h>
#include <cuda_fp16.h>
#include <cstdint>

// Problem constants
#define BB   8
#define LL   1024
#define DIN  512
#define HH   8
#define DD   64
#define DOUT 512
#define MM   (BB * LL)   // 8192

// Half-precision staging buffers
__device__ __half g_xh[3 * MM * DIN];       // inputs converted to half (24 MB)
__device__ __half g_wth[3 * DIN * DOUT];    // Wt[n][k] half; WQ pre-scaled by 0.125*log2e
__device__ __half g_q [BB * HH * LL * DD];  // [b,h,l,d], pre-scaled
__device__ __half g_k [BB * HH * LL * DD];  // [b,h,l,d]
__device__ __half g_vt[BB * HH * DD * LL];  // [b,h,d,l]  (V transposed)

// ===========================================================================
// Helpers
// ===========================================================================
__device__ __forceinline__ float ex2f(float x) {
    float y;
    asm("ex2.approx.ftz.f32 %0, %1;" : "=f"(y) : "f"(x));
    return y;
}

__device__ __forceinline__ void mma_f16_16n8k16(float& d0, float& d1, float& d2, float& d3,
                                                uint32_t a0, uint32_t a1, uint32_t a2, uint32_t a3,
                                                uint32_t b0, uint32_t b1) {
    asm volatile(
        "mma.sync.aligned.m16n8k16.row.col.f32.f16.f16.f32 "
        "{%0,%1,%2,%3}, {%4,%5,%6,%7}, {%8,%9}, {%0,%1,%2,%3};"
        : "+f"(d0), "+f"(d1), "+f"(d2), "+f"(d3)
        : "r"(a0), "r"(a1), "r"(a2), "r"(a3), "r"(b0), "r"(b1));
}

__device__ __forceinline__ uint32_t smem_u32(const void* p) {
    uint32_t a;
    asm("{ .reg .u64 t; cvta.to.shared.u64 t, %1; cvt.u32.u64 %0, t; }"
        : "=r"(a) : "l"(p));
    return a;
}

#define CP_ASYNC16(dst_u32, src_ptr) \
    asm volatile("cp.async.cg.shared.global [%0], [%1], 16;" :: "r"(dst_u32), "l"(src_ptr))
#define CP_COMMIT()  asm volatile("cp.async.commit_group;" ::: "memory")
#define CP_WAIT0()   asm volatile("cp.async.wait_group 0;" ::: "memory")

// ===========================================================================
// Convert inputs to half: g_xh[z] = half(X_z)
// ===========================================================================
__global__ void convert_x(const float* __restrict__ Q, const float* __restrict__ K,
                          const float* __restrict__ V)
{
    const float* src = (blockIdx.z == 0) ? Q : (blockIdx.z == 1) ? K : V;
    __half2* dst = (__half2*)(g_xh + (size_t)blockIdx.z * MM * DIN);
    const int i = blockIdx.x * blockDim.x + threadIdx.x;   // float4 index
    const float4 v = ((const float4*)src)[i];
    dst[2 * i + 0] = __floats2half2_rn(v.x, v.y);
    dst[2 * i + 1] = __floats2half2_rn(v.z, v.w);
}

// ===========================================================================
// Weight transpose + convert: Wt[n][k] = half(W[k][n] * s), s folds softmax
// scale (and log2e) into WQ.
// ===========================================================================
__global__ void transpose_w(const float* __restrict__ Wq,
                            const float* __restrict__ Wk,
                            const float* __restrict__ Wv)
{
    const float* W = (blockIdx.z == 0) ? Wq : (blockIdx.z == 1) ? Wk : Wv;
    __half* Wt = g_wth + (size_t)blockIdx.z * DIN * DOUT;
    const float s = (blockIdx.z == 0) ? 0.125f * 1.4426950408889634f : 1.0f;

    __shared__ float t[32][33];
    const int tx = threadIdx.x, ty = threadIdx.y;
    int x = blockIdx.x * 32 + tx;
    int y = blockIdx.y * 32 + ty;
    #pragma unroll
    for (int j = 0; j < 32; j += 8)
        t[ty + j][tx] = W[(size_t)(y + j) * DOUT + x];
    __syncthreads();
    x = blockIdx.y * 32 + tx;
    y = blockIdx.x * 32 + ty;
    #pragma unroll
    for (int j = 0; j < 32; j += 8)
        Wt[(size_t)(y + j) * DIN + x] = __float2half(t[tx][ty + j] * s);
}

// ===========================================================================
// fp16 mma.sync projection: Y = X @ W.
// CTA 128x128, K-chunk 64 (8 iters), double-buffered cp.async.
// smem rows padded to 72 halves (36 words) -> conflict-free fragments.
// Q/K outputs -> [b,h,l,d] half; V output -> [b,h,d,l] half (transposed).
// ===========================================================================
#define PTM 128
#define PTN 128
#define PTK 64
#define PKT (DIN / PTK)    // 8
#define PRH 72             // halves per smem row
#define PRW 36             // words per smem row
#define TILE_H (PTM * PRH) // halves per tile
#define SMEM_PROJ (4 * TILE_H * (int)sizeof(__half))   // 73728 B

__global__ __launch_bounds__(256)
void proj_mma_kernel()
{
    extern __shared__ __half smh[];
    __half* As[2] = { smh,              smh + TILE_H };
    __half* Bs[2] = { smh + 2 * TILE_H, smh + 3 * TILE_H };

    const int z = blockIdx.z;
    const __half* X  = g_xh  + (size_t)z * MM * DIN;
    const __half* Wt = g_wth + (size_t)z * DIN * DOUT;

    const int tid  = threadIdx.x;
    const int wid  = tid >> 5;
    const int lane = tid & 31;
    const int wm   = wid & 3;
    const int wn   = wid >> 2;
    const int m0   = blockIdx.y * PTM;
    const int n0   = blockIdx.x * PTN;
    const int lr   = lane >> 2;
    const int lc   = lane & 3;

    // cp.async slots: 4 chunks (16B = 8 halves) per tile per operand
    uint32_t dsto[4];
    const __half* a_src[4];
    const __half* b_src[4];
    #pragma unroll
    for (int i = 0; i < 4; i++) {
        const int idx = i * 256 + tid;
        const int r   = idx >> 3;       // 0..127
        const int c8  = idx & 7;        // 0..7
        dsto[i] = (uint32_t)((r * PRH + c8 * 8) * 2);
        a_src[i] = &X [(size_t)(m0 + r) * DIN + c8 * 8];
        b_src[i] = &Wt[(size_t)(n0 + r) * DIN + c8 * 8];
    }
    const uint32_t sa[2] = { smem_u32(As[0]), smem_u32(As[1]) };
    const uint32_t sb[2] = { smem_u32(Bs[0]), smem_u32(Bs[1]) };

    float acc[2][8][4];
    #pragma unroll
    for (int mt = 0; mt < 2; mt++)
        #pragma unroll
        for (int nt = 0; nt < 8; nt++)
            #pragma unroll
            for (int q = 0; q < 4; q++) acc[mt][nt][q] = 0.0f;

    #pragma unroll
    for (int i = 0; i < 4; i++) {
        CP_ASYNC16(sa[0] + dsto[i], a_src[i]);
        CP_ASYNC16(sb[0] + dsto[i], b_src[i]);
    }
    CP_COMMIT();
    CP_WAIT0();
    __syncthreads();

    for (int kt = 0; kt < PKT; kt++) {
        const int cur = kt & 1;
        if (kt + 1 < PKT) {
            const int nxt = cur ^ 1;
            const int koff = (kt + 1) * PTK;
            #pragma unroll
            for (int i = 0; i < 4; i++) {
                CP_ASYNC16(sa[nxt] + dsto[i], a_src[i] + koff);
                CP_ASYNC16(sb[nxt] + dsto[i], b_src[i] + koff);
            }
            CP_COMMIT();
        }

        const uint32_t* Aw = (const uint32_t*)As[cur];
        const uint32_t* Bw = (const uint32_t*)Bs[cur];
        #pragma unroll
        for (int ks = 0; ks < 4; ks++) {
            const int kw = ks * 8;   // word offset of this k16 step
            uint32_t af[2][4];
            #pragma unroll
            for (int mt = 0; mt < 2; mt++) {
                const int rb = wm * 32 + mt * 16 + lr;
                af[mt][0] = Aw[ rb      * PRW + kw + lc    ];
                af[mt][1] = Aw[(rb + 8) * PRW + kw + lc    ];
                af[mt][2] = Aw[ rb      * PRW + kw + lc + 4];
                af[mt][3] = Aw[(rb + 8) * PRW + kw + lc + 4];
            }
            uint32_t bf[8][2];
            #pragma unroll
            for (int nt = 0; nt < 8; nt++) {
                const int nb = wn * 64 + nt * 8 + lr;
                bf[nt][0] = Bw[nb * PRW + kw + lc    ];
                bf[nt][1] = Bw[nb * PRW + kw + lc + 4];
            }
            #pragma unroll
            for (int mt = 0; mt < 2; mt++)
                #pragma unroll
                for (int nt = 0; nt < 8; nt++)
                    mma_f16_16n8k16(acc[mt][nt][0], acc[mt][nt][1],
                                    acc[mt][nt][2], acc[mt][nt][3],
                                    af[mt][0], af[mt][1], af[mt][2], af[mt][3],
                                    bf[nt][0], bf[nt][1]);
        }

        if (kt + 1 < PKT) CP_WAIT0();
        __syncthreads();
    }

    // Epilogue
    if (z < 2) {
        __half* out = (z == 0) ? g_q : g_k;
        #pragma unroll
        for (int mt = 0; mt < 2; mt++) {
            #pragma unroll
            for (int nt = 0; nt < 8; nt++) {
                const int n  = n0 + wn * 64 + nt * 8 + 2 * lc;
                const int h  = n >> 6;
                const int d  = n & 63;
                const int m1 = m0 + wm * 32 + mt * 16 + lr;
                const int b1 = m1 >> 10, l1 = m1 & 1023;
                *(__half2*)&out[(((size_t)(b1 * HH + h) * LL + l1) * DD) + d] =
                    __floats2half2_rn(acc[mt][nt][0], acc[mt][nt][1]);
                const int m2 = m1 + 8;
                const int b2 = m2 >> 10, l2 = m2 & 1023;
                *(__half2*)&out[(((size_t)(b2 * HH + h) * LL + l2) * DD) + d] =
                    __floats2half2_rn(acc[mt][nt][2], acc[mt][nt][3]);
            }
        }
    } else {
        // V: store transposed [b,h,d,l]
        #pragma unroll
        for (int mt = 0; mt < 2; mt++) {
            #pragma unroll
            for (int nt = 0; nt < 8; nt++) {
                const int n  = n0 + wn * 64 + nt * 8 + 2 * lc;
                const int h  = n >> 6;
                const int d  = n & 63;
                const int m1 = m0 + wm * 32 + mt * 16 + lr;
                const int b1 = m1 >> 10, l1 = m1 & 1023;
                __half* base1 = &g_vt[((size_t)(b1 * HH + h) * DD + d) * LL + l1];
                base1[0]  = __float2half(acc[mt][nt][0]);
                base1[LL] = __float2half(acc[mt][nt][1]);
                const int m2 = m1 + 8;
                const int b2 = m2 >> 10, l2 = m2 & 1023;
                __half* base2 = &g_vt[((size_t)(b2 * HH + h) * DD + d) * LL + l2];
                base2[0]  = __float2half(acc[mt][nt][2]);
                base2[LL] = __float2half(acc[mt][nt][3]);
            }
        }
    }
}

// ===========================================================================
// Flash attention, fp16 m16n8k16, cp.async double-buffered K/Vt.
// CTA = (bh, 128-q tile); 8 warps x 16 q-rows; key tiles of 64.
// Q pre-scaled (in weights). K: [kc][d] half pad 72. Vt: [d][kc] half pad 72.
// QP: Q tile then P buffer, [128][72] half.
// ===========================================================================
#define AQT  128
#define AKT  64
#define KVH  (AKT * PRH)          // halves per K/Vt tile
#define QPH  (AQT * PRH)
#define SMEM_ATTN ((4 * KVH + QPH) * (int)sizeof(__half))   // 55296 B

__global__ __launch_bounds__(256, 2)
void attn_mma_kernel(float* __restrict__ out)
{
    extern __shared__ __half smh[];
    __half* Ksb[2] = { smh,           smh + KVH };
    __half* Vsb[2] = { smh + 2 * KVH, smh + 3 * KVH };
    __half* QP     = smh + 4 * KVH;

    const int it = (int)gridDim.x - 1 - (int)blockIdx.x;   // heavy tiles first
    const int bh = blockIdx.y;
    const int b  = bh >> 3;
    const int h  = bh & 7;

    const __half* Qb  = g_q  + (size_t)bh * LL * DD;
    const __half* Kb  = g_k  + (size_t)bh * LL * DD;
    const __half* Vtb = g_vt + (size_t)bh * DD * LL;

    const int tid  = threadIdx.x;
    const int wid  = tid >> 5;
    const int lane = tid & 31;
    const int lr   = lane >> 2;
    const int lc   = lane & 3;
    const int q0   = it * AQT;
    const int wq   = wid * 16;

    // cp.async slots: K/Vt tiles are 64 rows x 8 chunks -> 2 per thread;
    // Q tile is 128 rows x 8 chunks -> 4 per thread.
    uint32_t kv_dst[2];
    int kv_kc[2], kv_c8[2];
    #pragma unroll
    for (int i = 0; i < 2; i++) {
        const int idx = i * 256 + tid;
        kv_kc[i]  = idx >> 3;
        kv_c8[i]  = idx & 7;
        kv_dst[i] = (uint32_t)((kv_kc[i] * PRH + kv_c8[i] * 8) * 2);
    }
    const uint32_t sk[2] = { smem_u32(Ksb[0]), smem_u32(Ksb[1]) };
    const uint32_t sv[2] = { smem_u32(Vsb[0]), smem_u32(Vsb[1]) };
    const uint32_t sq    = smem_u32(QP);

    // Prologue: Q tile + key tile 0
    #pragma unroll
    for (int i = 0; i < 4; i++) {
        const int idx = i * 256 + tid;
        const int r = idx >> 3;
        const int c8 = idx & 7;
        CP_ASYNC16(sq + (uint32_t)((r * PRH + c8 * 8) * 2),
                   &Qb[(size_t)(q0 + r) * DD + c8 * 8]);
    }
    #pragma unroll
    for (int i = 0; i < 2; i++) {
        CP_ASYNC16(sk[0] + kv_dst[i], &Kb [(size_t)kv_kc[i] * DD + kv_c8[i] * 8]);
        CP_ASYNC16(sv[0] + kv_dst[i], &Vtb[(size_t)kv_kc[i] * LL + kv_c8[i] * 8]);
    }
    CP_COMMIT();
    CP_WAIT0();
    __syncthreads();

    // Build Q fragments (held in registers; 16 regs)
    uint32_t qf[4][4];
    {
        const uint32_t* Qw = (const uint32_t*)QP;
        #pragma unroll
        for (int ks = 0; ks < 4; ks++) {
            const int row = wq + lr;
            qf[ks][0] = Qw[ row      * PRW + ks * 8 + lc    ];
            qf[ks][1] = Qw[(row + 8) * PRW + ks * 8 + lc    ];
            qf[ks][2] = Qw[ row      * PRW + ks * 8 + lc + 4];
            qf[ks][3] = Qw[(row + 8) * PRW + ks * 8 + lc + 4];
        }
    }
    __syncthreads();   // QP becomes the P buffer

    float oa[8][4];
    #pragma unroll
    for (int nt = 0; nt < 8; nt++)
        #pragma unroll
        for (int q = 0; q < 4; q++) oa[nt][q] = 0.0f;
    float m0v = -1e30f, m1v = -1e30f, l0 = 0.0f, l1 = 0.0f;

    const int jmax = 2 * it + 1;
    for (int jt = 0; jt <= jmax; jt++) {
        const int cur = jt & 1;

        if (jt < jmax) {
            const int nxt = cur ^ 1;
            const size_t kbase = (size_t)(jt + 1) * AKT;
            #pragma unroll
            for (int i = 0; i < 2; i++) {
                CP_ASYNC16(sk[nxt] + kv_dst[i],
                           &Kb[(kbase + kv_kc[i]) * DD + kv_c8[i] * 8]);
                CP_ASYNC16(sv[nxt] + kv_dst[i],
                           &Vtb[(size_t)kv_kc[i] * LL + kbase + kv_c8[i] * 8]);
            }
            CP_COMMIT();
        }

        const uint32_t* Kw = (const uint32_t*)Ksb[cur];
        const uint32_t* Vw = (const uint32_t*)Vsb[cur];

        // ---- S = Q K^T ----
        float sa2[8][4];
        #pragma unroll
        for (int nt = 0; nt < 8; nt++)
            #pragma unroll
            for (int q = 0; q < 4; q++) sa2[nt][q] = 0.0f;

        #pragma unroll
        for (int ks = 0; ks < 4; ks++) {
            uint32_t bf[8][2];
            #pragma unroll
            for (int nt = 0; nt < 8; nt++) {
                const int nb = nt * 8 + lr;
                bf[nt][0] = Kw[nb * PRW + ks * 8 + lc    ];
                bf[nt][1] = Kw[nb * PRW + ks * 8 + lc + 4];
            }
            #pragma unroll
            for (int nt = 0; nt < 8; nt++)
                mma_f16_16n8k16(sa2[nt][0], sa2[nt][1], sa2[nt][2], sa2[nt][3],
                                qf[ks][0], qf[ks][1], qf[ks][2], qf[ks][3],
                                bf[nt][0], bf[nt][1]);
        }

        // ---- Causal mask ----
        const int qg0 = q0 + wq + lr;
        const int qg1 = qg0 + 8;
        if (jt * AKT + AKT - 1 > q0 + wq) {
            #pragma unroll
            for (int nt = 0; nt < 8; nt++) {
                const int kc0 = jt * AKT + nt * 8 + 2 * lc;
                if (kc0     > qg0) sa2[nt][0] = -1e30f;
                if (kc0 + 1 > qg0) sa2[nt][1] = -1e30f;
                if (kc0     > qg1) sa2[nt][2] = -1e30f;
                if (kc0 + 1 > qg1) sa2[nt][3] = -1e30f;
            }
        }

        // ---- Online softmax (log2 domain; scores already *log2e*scale) ----
        float tmax0 = -1e30f, tmax1 = -1e30f;
        #pragma unroll
        for (int nt = 0; nt < 8; nt++) {
            tmax0 = fmaxf(tmax0, fmaxf(sa2[nt][0], sa2[nt][1]));
            tmax1 = fmaxf(tmax1, fmaxf(sa2[nt][2], sa2[nt][3]));
        }
        tmax0 = fmaxf(tmax0, __shfl_xor_sync(0xffffffffu, tmax0, 1));
        tmax0 = fmaxf(tmax0, __shfl_xor_sync(0xffffffffu, tmax0, 2));
        tmax1 = fmaxf(tmax1, __shfl_xor_sync(0xffffffffu, tmax1, 1));
        tmax1 = fmaxf(tmax1, __shfl_xor_sync(0xffffffffu, tmax1, 2));

        const float mn0 = fmaxf(m0v, tmax0);
        const float mn1 = fmaxf(m1v, tmax1);
        const float f0  = ex2f(m0v - mn0);
        const float f1  = ex2f(m1v - mn1);

        float rs0 = 0.0f, rs1 = 0.0f;
        #pragma unroll
        for (int nt = 0; nt < 8; nt++) {
            const float p00 = ex2f(sa2[nt][0] - mn0);
            const float p01 = ex2f(sa2[nt][1] - mn0);
            const float p10 = ex2f(sa2[nt][2] - mn1);
            const float p11 = ex2f(sa2[nt][3] - mn1);
            rs0 += p00 + p01;
            rs1 += p10 + p11;
            *(__half2*)&QP[(wq + lr    ) * PRH + nt * 8 + 2 * lc] = __floats2half2_rn(p00, p01);
            *(__half2*)&QP[(wq + lr + 8) * PRH + nt * 8 + 2 * lc] = __floats2half2_rn(p10, p11);
        }
        rs0 += __shfl_xor_sync(0xffffffffu, rs0, 1);
        rs0 += __shfl_xor_sync(0xffffffffu, rs0, 2);
        rs1 += __shfl_xor_sync(0xffffffffu, rs1, 1);
        rs1 += __shfl_xor_sync(0xffffffffu, rs1, 2);

        l0 = l0 * f0 + rs0;  m0v = mn0;
        l1 = l1 * f1 + rs1;  m1v = mn1;
        #pragma unroll
        for (int nt = 0; nt < 8; nt++) {
            oa[nt][0] *= f0;  oa[nt][1] *= f0;
            oa[nt][2] *= f1;  oa[nt][3] *= f1;
        }
        __syncwarp();

        // ---- O += P V  (A from warp-private P rows; B from Vt[d][kc]) ----
        {
            const uint32_t* Pw = (const uint32_t*)QP;
            #pragma unroll
            for (int ks = 0; ks < 4; ks++) {
                uint32_t pf[4];
                pf[0] = Pw[(wq + lr    ) * PRW + ks * 8 + lc    ];
                pf[1] = Pw[(wq + lr + 8) * PRW + ks * 8 + lc    ];
                pf[2] = Pw[(wq + lr    ) * PRW + ks * 8 + lc + 4];
                pf[3] = Pw[(wq + lr + 8) * PRW + ks * 8 + lc + 4];
                uint32_t vf[8][2];
                #pragma unroll
                for (int nt = 0; nt < 8; nt++) {
                    const int nb = nt * 8 + lr;
                    vf[nt][0] = Vw[nb * PRW + ks * 8 + lc    ];
                    vf[nt][1] = Vw[nb * PRW + ks * 8 + lc + 4];
                }
                #pragma unroll
                for (int nt = 0; nt < 8; nt++)
                    mma_f16_16n8k16(oa[nt][0], oa[nt][1], oa[nt][2], oa[nt][3],
                                    pf[0], pf[1], pf[2], pf[3],
                                    vf[nt][0], vf[nt][1]);
            }
        }

        if (jt < jmax) CP_WAIT0();
        __syncthreads();
    }

    // ---- Epilogue (fp32 out) ----
    const float inv0 = 1.0f / l0;
    const float inv1 = 1.0f / l1;
    const int q1 = q0 + wq + lr;
    const int q2 = q1 + 8;
    #pragma unroll
    for (int nt = 0; nt < 8; nt++) {
        const int d = nt * 8 + 2 * lc;
        *(float2*)&out[((size_t)(b * LL + q1)) * DOUT + h * DD + d] =
            make_float2(oa[nt][0] * inv0, oa[nt][1] * inv0);
        *(float2*)&out[((size_t)(b * LL + q2)) * DOUT + h * DD + d] =
            make_float2(oa[nt][2] * inv1, oa[nt][3] * inv1);
    }
}

// ---------------------------------------------------------------------------
extern "C" void kernel_launch(void* const* d_in, const int* in_sizes, int n_in,
                              void* d_out, int out_size)
{
    const float* Qseq = (const float*)d_in[0];
    const float* Kseq = (const float*)d_in[1];
    const float* Vseq = (const float*)d_in[2];
    const float* WQ   = (const float*)d_in[3];
    const float* WK   = (const float*)d_in[4];
    const float* WV   = (const float*)d_in[5];
    float* out = (float*)d_out;

    cudaFuncSetAttribute(proj_mma_kernel,
                         cudaFuncAttributeMaxDynamicSharedMemorySize, SMEM_PROJ);
    cudaFuncSetAttribute(attn_mma_kernel,
                         cudaFuncAttributeMaxDynamicSharedMemorySize, SMEM_ATTN);

    dim3 cgrd(MM * DIN / (4 * 256), 1, 3);   // (4096,1,3)
    convert_x<<<cgrd, 256>>>(Qseq, Kseq, Vseq);

    dim3 tblk(32, 8);
    dim3 tgrd(DOUT / 32, DIN / 32, 3);
    transpose_w<<<tgrd, tblk>>>(WQ, WK, WV);

    dim3 pgrd(DOUT / PTN, MM / PTM, 3);      // (4, 64, 3)
    proj_mma_kernel<<<pgrd, 256, SMEM_PROJ>>>();

    dim3 agrd(LL / AQT, BB * HH);            // (8, 64)
    attn_mma_kernel<<<agrd, 256, SMEM_ATTN>>>(out);
}

// round 9
// speedup vs baseline: 5.2423x; 1.1058x over previous
#include <cuda_runtime.h>
#include <cuda_fp16.h>
#include <cstdint>

// Problem constants
#define BB   8
#define LL   1024
#define DIN  512
#define HH   8
#define DD   64
#define DOUT 512
#define MM   (BB * LL)   // 8192

// Half-precision staging buffers
__device__ __half g_xh[3 * MM * DIN];       // inputs converted to half
__device__ __half g_wth[3 * DIN * DOUT];    // Wt[n][k] half; WQ pre-scaled by 0.125*log2e
__device__ __half g_q [BB * HH * LL * DD];  // [b,h,l,d], pre-scaled
__device__ __half g_k [BB * HH * LL * DD];  // [b,h,l,d]
__device__ __half g_vt[BB * HH * DD * LL];  // [b,h,d,l]  (V transposed)

// ===========================================================================
// Helpers
// ===========================================================================
__device__ __forceinline__ float ex2f(float x) {
    float y;
    asm("ex2.approx.ftz.f32 %0, %1;" : "=f"(y) : "f"(x));
    return y;
}

__device__ __forceinline__ void mma_f16_16n8k16(float& d0, float& d1, float& d2, float& d3,
                                                uint32_t a0, uint32_t a1, uint32_t a2, uint32_t a3,
                                                uint32_t b0, uint32_t b1) {
    asm volatile(
        "mma.sync.aligned.m16n8k16.row.col.f32.f16.f16.f32 "
        "{%0,%1,%2,%3}, {%4,%5,%6,%7}, {%8,%9}, {%0,%1,%2,%3};"
        : "+f"(d0), "+f"(d1), "+f"(d2), "+f"(d3)
        : "r"(a0), "r"(a1), "r"(a2), "r"(a3), "r"(b0), "r"(b1));
}

__device__ __forceinline__ uint32_t smem_u32(const void* p) {
    uint32_t a;
    asm("{ .reg .u64 t; cvta.to.shared.u64 t, %1; cvt.u32.u64 %0, t; }"
        : "=r"(a) : "l"(p));
    return a;
}

#define CP_ASYNC16(dst_u32, src_ptr) \
    asm volatile("cp.async.cg.shared.global [%0], [%1], 16;" :: "r"(dst_u32), "l"(src_ptr))
#define CP_COMMIT()  asm volatile("cp.async.commit_group;" ::: "memory")
#define CP_WAIT0()   asm volatile("cp.async.wait_group 0;" ::: "memory")

// ===========================================================================
// Fused pre-pass: convert X->half AND transpose/convert W, one launch.
// grid = (4096 + 256, 1, 3), block = 256.
//   bx < 4096 : convert 1024 floats of X_z (float4 per thread)
//   bx >= 4096: transpose one 32x32 tile of W_z (threads as 32x8)
// ===========================================================================
__global__ void prepass_kernel(const float* __restrict__ Q, const float* __restrict__ K,
                               const float* __restrict__ V,
                               const float* __restrict__ Wq, const float* __restrict__ Wk,
                               const float* __restrict__ Wv)
{
    const int z  = blockIdx.z;
    const int bx = blockIdx.x;
    const int tid = threadIdx.x;

    if (bx < 4096) {
        const float* src = (z == 0) ? Q : (z == 1) ? K : V;
        __half2* dst = (__half2*)(g_xh + (size_t)z * MM * DIN);
        const int i = bx * 256 + tid;
        const float4 v = ((const float4*)src)[i];
        dst[2 * i + 0] = __floats2half2_rn(v.x, v.y);
        dst[2 * i + 1] = __floats2half2_rn(v.z, v.w);
    } else {
        const float* W = (z == 0) ? Wq : (z == 1) ? Wk : Wv;
        __half* Wt = g_wth + (size_t)z * DIN * DOUT;
        const float s = (z == 0) ? 0.125f * 1.4426950408889634f : 1.0f;

        __shared__ float t[32][33];
        const int tile = bx - 4096;       // 0..255
        const int bxt  = tile & 15;       // n-tile
        const int byt  = tile >> 4;       // k-tile
        const int tx = tid & 31, ty = tid >> 5;
        int x = bxt * 32 + tx;
        int y = byt * 32 + ty;
        #pragma unroll
        for (int j = 0; j < 32; j += 8)
            t[ty + j][tx] = W[(size_t)(y + j) * DOUT + x];
        __syncthreads();
        x = byt * 32 + tx;
        y = bxt * 32 + ty;
        #pragma unroll
        for (int j = 0; j < 32; j += 8)
            Wt[(size_t)(y + j) * DIN + x] = __float2half(t[tx][ty + j] * s);
    }
}

// ===========================================================================
// fp16 mma.sync projection: Y = X @ W.  (validated round 8)
// ===========================================================================
#define PTM 128
#define PTN 128
#define PTK 64
#define PKT (DIN / PTK)    // 8
#define PRH 72             // halves per smem row
#define PRW 36             // words per smem row
#define TILE_H (PTM * PRH)
#define SMEM_PROJ (4 * TILE_H * (int)sizeof(__half))   // 73728 B

__global__ __launch_bounds__(256)
void proj_mma_kernel()
{
    extern __shared__ __half smh[];
    __half* As[2] = { smh,              smh + TILE_H };
    __half* Bs[2] = { smh + 2 * TILE_H, smh + 3 * TILE_H };

    const int z = blockIdx.z;
    const __half* X  = g_xh  + (size_t)z * MM * DIN;
    const __half* Wt = g_wth + (size_t)z * DIN * DOUT;

    const int tid  = threadIdx.x;
    const int wid  = tid >> 5;
    const int lane = tid & 31;
    const int wm   = wid & 3;
    const int wn   = wid >> 2;
    const int m0   = blockIdx.y * PTM;
    const int n0   = blockIdx.x * PTN;
    const int lr   = lane >> 2;
    const int lc   = lane & 3;

    uint32_t dsto[4];
    const __half* a_src[4];
    const __half* b_src[4];
    #pragma unroll
    for (int i = 0; i < 4; i++) {
        const int idx = i * 256 + tid;
        const int r   = idx >> 3;
        const int c8  = idx & 7;
        dsto[i] = (uint32_t)((r * PRH + c8 * 8) * 2);
        a_src[i] = &X [(size_t)(m0 + r) * DIN + c8 * 8];
        b_src[i] = &Wt[(size_t)(n0 + r) * DIN + c8 * 8];
    }
    const uint32_t sa[2] = { smem_u32(As[0]), smem_u32(As[1]) };
    const uint32_t sb[2] = { smem_u32(Bs[0]), smem_u32(Bs[1]) };

    float acc[2][8][4];
    #pragma unroll
    for (int mt = 0; mt < 2; mt++)
        #pragma unroll
        for (int nt = 0; nt < 8; nt++)
            #pragma unroll
            for (int q = 0; q < 4; q++) acc[mt][nt][q] = 0.0f;

    #pragma unroll
    for (int i = 0; i < 4; i++) {
        CP_ASYNC16(sa[0] + dsto[i], a_src[i]);
        CP_ASYNC16(sb[0] + dsto[i], b_src[i]);
    }
    CP_COMMIT();
    CP_WAIT0();
    __syncthreads();

    for (int kt = 0; kt < PKT; kt++) {
        const int cur = kt & 1;
        if (kt + 1 < PKT) {
            const int nxt = cur ^ 1;
            const int koff = (kt + 1) * PTK;
            #pragma unroll
            for (int i = 0; i < 4; i++) {
                CP_ASYNC16(sa[nxt] + dsto[i], a_src[i] + koff);
                CP_ASYNC16(sb[nxt] + dsto[i], b_src[i] + koff);
            }
            CP_COMMIT();
        }

        const uint32_t* Aw = (const uint32_t*)As[cur];
        const uint32_t* Bw = (const uint32_t*)Bs[cur];
        #pragma unroll
        for (int ks = 0; ks < 4; ks++) {
            const int kw = ks * 8;
            uint32_t af[2][4];
            #pragma unroll
            for (int mt = 0; mt < 2; mt++) {
                const int rb = wm * 32 + mt * 16 + lr;
                af[mt][0] = Aw[ rb      * PRW + kw + lc    ];
                af[mt][1] = Aw[(rb + 8) * PRW + kw + lc    ];
                af[mt][2] = Aw[ rb      * PRW + kw + lc + 4];
                af[mt][3] = Aw[(rb + 8) * PRW + kw + lc + 4];
            }
            uint32_t bf[8][2];
            #pragma unroll
            for (int nt = 0; nt < 8; nt++) {
                const int nb = wn * 64 + nt * 8 + lr;
                bf[nt][0] = Bw[nb * PRW + kw + lc    ];
                bf[nt][1] = Bw[nb * PRW + kw + lc + 4];
            }
            #pragma unroll
            for (int mt = 0; mt < 2; mt++)
                #pragma unroll
                for (int nt = 0; nt < 8; nt++)
                    mma_f16_16n8k16(acc[mt][nt][0], acc[mt][nt][1],
                                    acc[mt][nt][2], acc[mt][nt][3],
                                    af[mt][0], af[mt][1], af[mt][2], af[mt][3],
                                    bf[nt][0], bf[nt][1]);
        }

        if (kt + 1 < PKT) CP_WAIT0();
        __syncthreads();
    }

    if (z < 2) {
        __half* out = (z == 0) ? g_q : g_k;
        #pragma unroll
        for (int mt = 0; mt < 2; mt++) {
            #pragma unroll
            for (int nt = 0; nt < 8; nt++) {
                const int n  = n0 + wn * 64 + nt * 8 + 2 * lc;
                const int h  = n >> 6;
                const int d  = n & 63;
                const int m1 = m0 + wm * 32 + mt * 16 + lr;
                const int b1 = m1 >> 10, l1 = m1 & 1023;
                *(__half2*)&out[(((size_t)(b1 * HH + h) * LL + l1) * DD) + d] =
                    __floats2half2_rn(acc[mt][nt][0], acc[mt][nt][1]);
                const int m2 = m1 + 8;
                const int b2 = m2 >> 10, l2 = m2 & 1023;
                *(__half2*)&out[(((size_t)(b2 * HH + h) * LL + l2) * DD) + d] =
                    __floats2half2_rn(acc[mt][nt][2], acc[mt][nt][3]);
            }
        }
    } else {
        #pragma unroll
        for (int mt = 0; mt < 2; mt++) {
            #pragma unroll
            for (int nt = 0; nt < 8; nt++) {
                const int n  = n0 + wn * 64 + nt * 8 + 2 * lc;
                const int h  = n >> 6;
                const int d  = n & 63;
                const int m1 = m0 + wm * 32 + mt * 16 + lr;
                const int b1 = m1 >> 10, l1 = m1 & 1023;
                __half* base1 = &g_vt[((size_t)(b1 * HH + h) * DD + d) * LL + l1];
                base1[0]  = __float2half(acc[mt][nt][0]);
                base1[LL] = __float2half(acc[mt][nt][1]);
                const int m2 = m1 + 8;
                const int b2 = m2 >> 10, l2 = m2 & 1023;
                __half* base2 = &g_vt[((size_t)(b2 * HH + h) * DD + d) * LL + l2];
                base2[0]  = __float2half(acc[mt][nt][2]);
                base2[LL] = __float2half(acc[mt][nt][3]);
            }
        }
    }
}

// ===========================================================================
// Flash attention, fp16 m16n8k16, cp.async double-buffered K/Vt.
// Balanced pairing: CTA p handles q-tiles (7-p) then (p) of the same bh.
// grid = (4, 64) = 256 CTAs -> ONE wave at 2 CTAs/SM, perfectly balanced
// (18 key-tile units per CTA). K/V re-reads on pass 2 hit L2.
// ===========================================================================
#define AQT  128
#define AKT  64
#define KVH  (AKT * PRH)
#define QPH  (AQT * PRH)
#define SMEM_ATTN ((4 * KVH + QPH) * (int)sizeof(__half))   // 55296 B

__global__ __launch_bounds__(256, 2)
void attn_mma_kernel(float* __restrict__ out)
{
    extern __shared__ __half smh[];
    __half* Ksb[2] = { smh,           smh + KVH };
    __half* Vsb[2] = { smh + 2 * KVH, smh + 3 * KVH };
    __half* QP     = smh + 4 * KVH;

    const int p  = blockIdx.x;          // 0..3
    const int bh = blockIdx.y;
    const int b  = bh >> 3;
    const int h  = bh & 7;

    const __half* Qb  = g_q  + (size_t)bh * LL * DD;
    const __half* Kb  = g_k  + (size_t)bh * LL * DD;
    const __half* Vtb = g_vt + (size_t)bh * DD * LL;

    const int tid  = threadIdx.x;
    const int wid  = tid >> 5;
    const int lane = tid & 31;
    const int lr   = lane >> 2;
    const int lc   = lane & 3;
    const int wq   = wid * 16;

    uint32_t kv_dst[2];
    int kv_kc[2], kv_c8[2];
    #pragma unroll
    for (int i = 0; i < 2; i++) {
        const int idx = i * 256 + tid;
        kv_kc[i]  = idx >> 3;
        kv_c8[i]  = idx & 7;
        kv_dst[i] = (uint32_t)((kv_kc[i] * PRH + kv_c8[i] * 8) * 2);
    }
    const uint32_t sk[2] = { smem_u32(Ksb[0]), smem_u32(Ksb[1]) };
    const uint32_t sv[2] = { smem_u32(Vsb[0]), smem_u32(Vsb[1]) };
    const uint32_t sq    = smem_u32(QP);

    for (int pass = 0; pass < 2; pass++) {
        const int it = pass ? p : (7 - p);
        const int q0 = it * AQT;

        // Prologue: Q tile + key tile 0 (sync: prior pass done with buffers)
        __syncthreads();
        #pragma unroll
        for (int i = 0; i < 4; i++) {
            const int idx = i * 256 + tid;
            const int r = idx >> 3;
            const int c8 = idx & 7;
            CP_ASYNC16(sq + (uint32_t)((r * PRH + c8 * 8) * 2),
                       &Qb[(size_t)(q0 + r) * DD + c8 * 8]);
        }
        #pragma unroll
        for (int i = 0; i < 2; i++) {
            CP_ASYNC16(sk[0] + kv_dst[i], &Kb [(size_t)kv_kc[i] * DD + kv_c8[i] * 8]);
            CP_ASYNC16(sv[0] + kv_dst[i], &Vtb[(size_t)kv_kc[i] * LL + kv_c8[i] * 8]);
        }
        CP_COMMIT();
        CP_WAIT0();
        __syncthreads();

        // Build Q fragments
        uint32_t qf[4][4];
        {
            const uint32_t* Qw = (const uint32_t*)QP;
            #pragma unroll
            for (int ks = 0; ks < 4; ks++) {
                const int row = wq + lr;
                qf[ks][0] = Qw[ row      * PRW + ks * 8 + lc    ];
                qf[ks][1] = Qw[(row + 8) * PRW + ks * 8 + lc    ];
                qf[ks][2] = Qw[ row      * PRW + ks * 8 + lc + 4];
                qf[ks][3] = Qw[(row + 8) * PRW + ks * 8 + lc + 4];
            }
        }
        __syncthreads();   // QP becomes P buffer

        float oa[8][4];
        #pragma unroll
        for (int nt = 0; nt < 8; nt++)
            #pragma unroll
            for (int q = 0; q < 4; q++) oa[nt][q] = 0.0f;
        float m0v = -1e30f, m1v = -1e30f, l0 = 0.0f, l1 = 0.0f;

        const int jmax = 2 * it + 1;
        for (int jt = 0; jt <= jmax; jt++) {
            const int cur = jt & 1;

            if (jt < jmax) {
                const int nxt = cur ^ 1;
                const size_t kbase = (size_t)(jt + 1) * AKT;
                #pragma unroll
                for (int i = 0; i < 2; i++) {
                    CP_ASYNC16(sk[nxt] + kv_dst[i],
                               &Kb[(kbase + kv_kc[i]) * DD + kv_c8[i] * 8]);
                    CP_ASYNC16(sv[nxt] + kv_dst[i],
                               &Vtb[(size_t)kv_kc[i] * LL + kbase + kv_c8[i] * 8]);
                }
                CP_COMMIT();
            }

            const uint32_t* Kw = (const uint32_t*)Ksb[cur];
            const uint32_t* Vw = (const uint32_t*)Vsb[cur];

            // ---- S = Q K^T ----
            float sa2[8][4];
            #pragma unroll
            for (int nt = 0; nt < 8; nt++)
                #pragma unroll
                for (int q = 0; q < 4; q++) sa2[nt][q] = 0.0f;

            #pragma unroll
            for (int ks = 0; ks < 4; ks++) {
                uint32_t bf[8][2];
                #pragma unroll
                for (int nt = 0; nt < 8; nt++) {
                    const int nb = nt * 8 + lr;
                    bf[nt][0] = Kw[nb * PRW + ks * 8 + lc    ];
                    bf[nt][1] = Kw[nb * PRW + ks * 8 + lc + 4];
                }
                #pragma unroll
                for (int nt = 0; nt < 8; nt++)
                    mma_f16_16n8k16(sa2[nt][0], sa2[nt][1], sa2[nt][2], sa2[nt][3],
                                    qf[ks][0], qf[ks][1], qf[ks][2], qf[ks][3],
                                    bf[nt][0], bf[nt][1]);
            }

            // ---- Causal mask ----
            const int qg0 = q0 + wq + lr;
            const int qg1 = qg0 + 8;
            if (jt * AKT + AKT - 1 > q0 + wq) {
                #pragma unroll
                for (int nt = 0; nt < 8; nt++) {
                    const int kc0 = jt * AKT + nt * 8 + 2 * lc;
                    if (kc0     > qg0) sa2[nt][0] = -1e30f;
                    if (kc0 + 1 > qg0) sa2[nt][1] = -1e30f;
                    if (kc0     > qg1) sa2[nt][2] = -1e30f;
                    if (kc0 + 1 > qg1) sa2[nt][3] = -1e30f;
                }
            }

            // ---- Online softmax (log2 domain) ----
            float tmax0 = -1e30f, tmax1 = -1e30f;
            #pragma unroll
            for (int nt = 0; nt < 8; nt++) {
                tmax0 = fmaxf(tmax0, fmaxf(sa2[nt][0], sa2[nt][1]));
                tmax1 = fmaxf(tmax1, fmaxf(sa2[nt][2], sa2[nt][3]));
            }
            tmax0 = fmaxf(tmax0, __shfl_xor_sync(0xffffffffu, tmax0, 1));
            tmax0 = fmaxf(tmax0, __shfl_xor_sync(0xffffffffu, tmax0, 2));
            tmax1 = fmaxf(tmax1, __shfl_xor_sync(0xffffffffu, tmax1, 1));
            tmax1 = fmaxf(tmax1, __shfl_xor_sync(0xffffffffu, tmax1, 2));

            const float mn0 = fmaxf(m0v, tmax0);
            const float mn1 = fmaxf(m1v, tmax1);
            const float f0  = ex2f(m0v - mn0);
            const float f1  = ex2f(m1v - mn1);

            float rs0 = 0.0f, rs1 = 0.0f;
            #pragma unroll
            for (int nt = 0; nt < 8; nt++) {
                const float p00 = ex2f(sa2[nt][0] - mn0);
                const float p01 = ex2f(sa2[nt][1] - mn0);
                const float p10 = ex2f(sa2[nt][2] - mn1);
                const float p11 = ex2f(sa2[nt][3] - mn1);
                rs0 += p00 + p01;
                rs1 += p10 + p11;
                *(__half2*)&QP[(wq + lr    ) * PRH + nt * 8 + 2 * lc] = __floats2half2_rn(p00, p01);
                *(__half2*)&QP[(wq + lr + 8) * PRH + nt * 8 + 2 * lc] = __floats2half2_rn(p10, p11);
            }
            rs0 += __shfl_xor_sync(0xffffffffu, rs0, 1);
            rs0 += __shfl_xor_sync(0xffffffffu, rs0, 2);
            rs1 += __shfl_xor_sync(0xffffffffu, rs1, 1);
            rs1 += __shfl_xor_sync(0xffffffffu, rs1, 2);

            l0 = l0 * f0 + rs0;  m0v = mn0;
            l1 = l1 * f1 + rs1;  m1v = mn1;
            #pragma unroll
            for (int nt = 0; nt < 8; nt++) {
                oa[nt][0] *= f0;  oa[nt][1] *= f0;
                oa[nt][2] *= f1;  oa[nt][3] *= f1;
            }
            __syncwarp();

            // ---- O += P V ----
            {
                const uint32_t* Pw = (const uint32_t*)QP;
                #pragma unroll
                for (int ks = 0; ks < 4; ks++) {
                    uint32_t pf[4];
                    pf[0] = Pw[(wq + lr    ) * PRW + ks * 8 + lc    ];
                    pf[1] = Pw[(wq + lr + 8) * PRW + ks * 8 + lc    ];
                    pf[2] = Pw[(wq + lr    ) * PRW + ks * 8 + lc + 4];
                    pf[3] = Pw[(wq + lr + 8) * PRW + ks * 8 + lc + 4];
                    uint32_t vf[8][2];
                    #pragma unroll
                    for (int nt = 0; nt < 8; nt++) {
                        const int nb = nt * 8 + lr;
                        vf[nt][0] = Vw[nb * PRW + ks * 8 + lc    ];
                        vf[nt][1] = Vw[nb * PRW + ks * 8 + lc + 4];
                    }
                    #pragma unroll
                    for (int nt = 0; nt < 8; nt++)
                        mma_f16_16n8k16(oa[nt][0], oa[nt][1], oa[nt][2], oa[nt][3],
                                        pf[0], pf[1], pf[2], pf[3],
                                        vf[nt][0], vf[nt][1]);
                }
            }

            if (jt < jmax) CP_WAIT0();
            __syncthreads();
        }

        // ---- Epilogue (fp32 out) ----
        const float inv0 = 1.0f / l0;
        const float inv1 = 1.0f / l1;
        const int q1 = q0 + wq + lr;
        const int q2 = q1 + 8;
        #pragma unroll
        for (int nt = 0; nt < 8; nt++) {
            const int d = nt * 8 + 2 * lc;
            *(float2*)&out[((size_t)(b * LL + q1)) * DOUT + h * DD + d] =
                make_float2(oa[nt][0] * inv0, oa[nt][1] * inv0);
            *(float2*)&out[((size_t)(b * LL + q2)) * DOUT + h * DD + d] =
                make_float2(oa[nt][2] * inv1, oa[nt][3] * inv1);
        }
    }
}

// ---------------------------------------------------------------------------
extern "C" void kernel_launch(void* const* d_in, const int* in_sizes, int n_in,
                              void* d_out, int out_size)
{
    const float* Qseq = (const float*)d_in[0];
    const float* Kseq = (const float*)d_in[1];
    const float* Vseq = (const float*)d_in[2];
    const float* WQ   = (const float*)d_in[3];
    const float* WK   = (const float*)d_in[4];
    const float* WV   = (const float*)d_in[5];
    float* out = (float*)d_out;

    cudaFuncSetAttribute(proj_mma_kernel,
                         cudaFuncAttributeMaxDynamicSharedMemorySize, SMEM_PROJ);
    cudaFuncSetAttribute(attn_mma_kernel,
                         cudaFuncAttributeMaxDynamicSharedMemorySize, SMEM_ATTN);

    dim3 ppgrd(4096 + 256, 1, 3);
    prepass_kernel<<<ppgrd, 256>>>(Qseq, Kseq, Vseq, WQ, WK, WV);

    dim3 pgrd(DOUT / PTN, MM / PTM, 3);      // (4, 64, 3)
    proj_mma_kernel<<<pgrd, 256, SMEM_PROJ>>>();

    dim3 agrd(4, BB * HH);                   // 256 CTAs, one balanced wave
    attn_mma_kernel<<<agrd, 256, SMEM_ATTN>>>(out);
}

// round 10
// speedup vs baseline: 6.4741x; 1.2350x over previous
#include <cuda_runtime.h>
#include <cuda_fp16.h>
#include <cstdint>

// Problem constants
#define BB   8
#define LL   1024
#define DIN  512
#define HH   8
#define DD   64
#define DOUT 512
#define MM   (BB * LL)   // 8192

// Half-precision staging buffers
__device__ __half g_xh[3 * MM * DIN];       // inputs converted to half
__device__ __half g_wth[3 * DIN * DOUT];    // Wt[n][k] half; WQ pre-scaled by 0.125*log2e
__device__ __half g_q [BB * HH * LL * DD];  // [b,h,l,d], pre-scaled
__device__ __half g_k [BB * HH * LL * DD];  // [b,h,l,d]
__device__ __half g_vt[BB * HH * DD * LL];  // [b,h,d,l]  (V transposed)

// ===========================================================================
// Helpers
// ===========================================================================
__device__ __forceinline__ float ex2f(float x) {
    float y;
    asm("ex2.approx.ftz.f32 %0, %1;" : "=f"(y) : "f"(x));
    return y;
}

__device__ __forceinline__ void mma_f16_16n8k16(float& d0, float& d1, float& d2, float& d3,
                                                uint32_t a0, uint32_t a1, uint32_t a2, uint32_t a3,
                                                uint32_t b0, uint32_t b1) {
    asm volatile(
        "mma.sync.aligned.m16n8k16.row.col.f32.f16.f16.f32 "
        "{%0,%1,%2,%3}, {%4,%5,%6,%7}, {%8,%9}, {%0,%1,%2,%3};"
        : "+f"(d0), "+f"(d1), "+f"(d2), "+f"(d3)
        : "r"(a0), "r"(a1), "r"(a2), "r"(a3), "r"(b0), "r"(b1));
}

__device__ __forceinline__ void ldmatrix_x4(uint32_t& r0, uint32_t& r1,
                                            uint32_t& r2, uint32_t& r3, uint32_t addr) {
    asm volatile("ldmatrix.sync.aligned.m8n8.x4.shared.b16 {%0,%1,%2,%3}, [%4];"
                 : "=r"(r0), "=r"(r1), "=r"(r2), "=r"(r3) : "r"(addr));
}

__device__ __forceinline__ uint32_t smem_u32(const void* p) {
    uint32_t a;
    asm("{ .reg .u64 t; cvta.to.shared.u64 t, %1; cvt.u32.u64 %0, t; }"
        : "=r"(a) : "l"(p));
    return a;
}

#define CP_ASYNC16(dst_u32, src_ptr) \
    asm volatile("cp.async.cg.shared.global [%0], [%1], 16;" :: "r"(dst_u32), "l"(src_ptr))
#define CP_COMMIT()  asm volatile("cp.async.commit_group;" ::: "memory")
#define CP_WAIT0()   asm volatile("cp.async.wait_group 0;" ::: "memory")

// ===========================================================================
// Fused pre-pass: convert X->half AND transpose/convert W, one launch.
// ===========================================================================
__global__ void prepass_kernel(const float* __restrict__ Q, const float* __restrict__ K,
                               const float* __restrict__ V,
                               const float* __restrict__ Wq, const float* __restrict__ Wk,
                               const float* __restrict__ Wv)
{
    const int z  = blockIdx.z;
    const int bx = blockIdx.x;
    const int tid = threadIdx.x;

    if (bx < 4096) {
        const float* src = (z == 0) ? Q : (z == 1) ? K : V;
        __half2* dst = (__half2*)(g_xh + (size_t)z * MM * DIN);
        const int i = bx * 256 + tid;
        const float4 v = ((const float4*)src)[i];
        dst[2 * i + 0] = __floats2half2_rn(v.x, v.y);
        dst[2 * i + 1] = __floats2half2_rn(v.z, v.w);
    } else {
        const float* W = (z == 0) ? Wq : (z == 1) ? Wk : Wv;
        __half* Wt = g_wth + (size_t)z * DIN * DOUT;
        const float s = (z == 0) ? 0.125f * 1.4426950408889634f : 1.0f;

        __shared__ float t[32][33];
        const int tile = bx - 4096;
        const int bxt  = tile & 15;
        const int byt  = tile >> 4;
        const int tx = tid & 31, ty = tid >> 5;
        int x = bxt * 32 + tx;
        int y = byt * 32 + ty;
        #pragma unroll
        for (int j = 0; j < 32; j += 8)
            t[ty + j][tx] = W[(size_t)(y + j) * DOUT + x];
        __syncthreads();
        x = byt * 32 + tx;
        y = bxt * 32 + ty;
        #pragma unroll
        for (int j = 0; j < 32; j += 8)
            Wt[(size_t)(y + j) * DIN + x] = __float2half(t[tx][ty + j] * s);
    }
}

// ===========================================================================
// fp16 mma.sync projection with ldmatrix fragment loads.
// ===========================================================================
#define PTM 128
#define PTN 128
#define PTK 64
#define PKT (DIN / PTK)    // 8
#define PRH 72             // halves per smem row
#define PRW 36             // words per smem row
#define TILE_H (PTM * PRH)
#define SMEM_PROJ (4 * TILE_H * (int)sizeof(__half))   // 73728 B

__global__ __launch_bounds__(256)
void proj_mma_kernel()
{
    extern __shared__ __half smh[];
    __half* As[2] = { smh,              smh + TILE_H };
    __half* Bs[2] = { smh + 2 * TILE_H, smh + 3 * TILE_H };

    const int z = blockIdx.z;
    const __half* X  = g_xh  + (size_t)z * MM * DIN;
    const __half* Wt = g_wth + (size_t)z * DIN * DOUT;

    const int tid  = threadIdx.x;
    const int wid  = tid >> 5;
    const int lane = tid & 31;
    const int wm   = wid & 3;
    const int wn   = wid >> 2;
    const int m0   = blockIdx.y * PTM;
    const int n0   = blockIdx.x * PTN;
    const int lr   = lane >> 2;
    const int lc   = lane & 3;

    // ldmatrix per-lane offsets
    const int a_row = ((lane >> 3) & 1) * 8 + (lane & 7);  // A: {m0,m1,m2,m3}={r,r+8}x{c,c+8}
    const int a_kh  = (lane >> 4) * 8;
    const int b_row = (lane >> 4) * 8 + (lane & 7);        // B pair: {n,n}{n+8,n+8} x {c,c+8}
    const int b_kh  = ((lane >> 3) & 1) * 8;

    uint32_t dsto[4];
    const __half* a_src[4];
    const __half* b_src[4];
    #pragma unroll
    for (int i = 0; i < 4; i++) {
        const int idx = i * 256 + tid;
        const int r   = idx >> 3;
        const int c8  = idx & 7;
        dsto[i] = (uint32_t)((r * PRH + c8 * 8) * 2);
        a_src[i] = &X [(size_t)(m0 + r) * DIN + c8 * 8];
        b_src[i] = &Wt[(size_t)(n0 + r) * DIN + c8 * 8];
    }
    const uint32_t sa[2] = { smem_u32(As[0]), smem_u32(As[1]) };
    const uint32_t sb[2] = { smem_u32(Bs[0]), smem_u32(Bs[1]) };

    float acc[2][8][4];
    #pragma unroll
    for (int mt = 0; mt < 2; mt++)
        #pragma unroll
        for (int nt = 0; nt < 8; nt++)
            #pragma unroll
            for (int q = 0; q < 4; q++) acc[mt][nt][q] = 0.0f;

    #pragma unroll
    for (int i = 0; i < 4; i++) {
        CP_ASYNC16(sa[0] + dsto[i], a_src[i]);
        CP_ASYNC16(sb[0] + dsto[i], b_src[i]);
    }
    CP_COMMIT();
    CP_WAIT0();
    __syncthreads();

    for (int kt = 0; kt < PKT; kt++) {
        const int cur = kt & 1;
        if (kt + 1 < PKT) {
            const int nxt = cur ^ 1;
            const int koff = (kt + 1) * PTK;
            #pragma unroll
            for (int i = 0; i < 4; i++) {
                CP_ASYNC16(sa[nxt] + dsto[i], a_src[i] + koff);
                CP_ASYNC16(sb[nxt] + dsto[i], b_src[i] + koff);
            }
            CP_COMMIT();
        }

        const uint32_t Abase = sa[cur];
        const uint32_t Bbase = sb[cur];
        #pragma unroll
        for (int ks = 0; ks < 4; ks++) {
            uint32_t af[2][4];
            #pragma unroll
            for (int mt = 0; mt < 2; mt++) {
                const uint32_t addr = Abase +
                    (uint32_t)(((wm * 32 + mt * 16 + a_row) * PRH + ks * 16 + a_kh) * 2);
                ldmatrix_x4(af[mt][0], af[mt][1], af[mt][2], af[mt][3], addr);
            }
            uint32_t bf[8][2];
            #pragma unroll
            for (int ntp = 0; ntp < 4; ntp++) {
                const uint32_t addr = Bbase +
                    (uint32_t)(((wn * 64 + ntp * 16 + b_row) * PRH + ks * 16 + b_kh) * 2);
                ldmatrix_x4(bf[2 * ntp][0], bf[2 * ntp][1],
                            bf[2 * ntp + 1][0], bf[2 * ntp + 1][1], addr);
            }
            #pragma unroll
            for (int mt = 0; mt < 2; mt++)
                #pragma unroll
                for (int nt = 0; nt < 8; nt++)
                    mma_f16_16n8k16(acc[mt][nt][0], acc[mt][nt][1],
                                    acc[mt][nt][2], acc[mt][nt][3],
                                    af[mt][0], af[mt][1], af[mt][2], af[mt][3],
                                    bf[nt][0], bf[nt][1]);
        }

        if (kt + 1 < PKT) CP_WAIT0();
        __syncthreads();
    }

    if (z < 2) {
        __half* out = (z == 0) ? g_q : g_k;
        #pragma unroll
        for (int mt = 0; mt < 2; mt++) {
            #pragma unroll
            for (int nt = 0; nt < 8; nt++) {
                const int n  = n0 + wn * 64 + nt * 8 + 2 * lc;
                const int h  = n >> 6;
                const int d  = n & 63;
                const int m1 = m0 + wm * 32 + mt * 16 + lr;
                const int b1 = m1 >> 10, l1 = m1 & 1023;
                *(__half2*)&out[(((size_t)(b1 * HH + h) * LL + l1) * DD) + d] =
                    __floats2half2_rn(acc[mt][nt][0], acc[mt][nt][1]);
                const int m2 = m1 + 8;
                const int b2 = m2 >> 10, l2 = m2 & 1023;
                *(__half2*)&out[(((size_t)(b2 * HH + h) * LL + l2) * DD) + d] =
                    __floats2half2_rn(acc[mt][nt][2], acc[mt][nt][3]);
            }
        }
    } else {
        #pragma unroll
        for (int mt = 0; mt < 2; mt++) {
            #pragma unroll
            for (int nt = 0; nt < 8; nt++) {
                const int n  = n0 + wn * 64 + nt * 8 + 2 * lc;
                const int h  = n >> 6;
                const int d  = n & 63;
                const int m1 = m0 + wm * 32 + mt * 16 + lr;
                const int b1 = m1 >> 10, l1 = m1 & 1023;
                __half* base1 = &g_vt[((size_t)(b1 * HH + h) * DD + d) * LL + l1];
                base1[0]  = __float2half(acc[mt][nt][0]);
                base1[LL] = __float2half(acc[mt][nt][1]);
                const int m2 = m1 + 8;
                const int b2 = m2 >> 10, l2 = m2 & 1023;
                __half* base2 = &g_vt[((size_t)(b2 * HH + h) * DD + d) * LL + l2];
                base2[0]  = __float2half(acc[mt][nt][2]);
                base2[LL] = __float2half(acc[mt][nt][3]);
            }
        }
    }
}

// ===========================================================================
// Flash attention, fp16 m16n8k16 + ldmatrix, balanced q-tile pairing.
// ===========================================================================
#define AQT  128
#define AKT  64
#define KVH  (AKT * PRH)
#define QPH  (AQT * PRH)
#define SMEM_ATTN ((4 * KVH + QPH) * (int)sizeof(__half))   // 55296 B

__global__ __launch_bounds__(256, 2)
void attn_mma_kernel(float* __restrict__ out)
{
    extern __shared__ __half smh[];
    __half* Ksb[2] = { smh,           smh + KVH };
    __half* Vsb[2] = { smh + 2 * KVH, smh + 3 * KVH };
    __half* QP     = smh + 4 * KVH;

    const int p  = blockIdx.x;          // 0..3
    const int bh = blockIdx.y;
    const int b  = bh >> 3;
    const int h  = bh & 7;

    const __half* Qb  = g_q  + (size_t)bh * LL * DD;
    const __half* Kb  = g_k  + (size_t)bh * LL * DD;
    const __half* Vtb = g_vt + (size_t)bh * DD * LL;

    const int tid  = threadIdx.x;
    const int wid  = tid >> 5;
    const int lane = tid & 31;
    const int lr   = lane >> 2;
    const int lc   = lane & 3;
    const int wq   = wid * 16;

    // ldmatrix per-lane offsets
    const int a_row = ((lane >> 3) & 1) * 8 + (lane & 7);
    const int a_kh  = (lane >> 4) * 8;
    const int b_row = (lane >> 4) * 8 + (lane & 7);
    const int b_kh  = ((lane >> 3) & 1) * 8;

    uint32_t kv_dst[2];
    int kv_kc[2], kv_c8[2];
    #pragma unroll
    for (int i = 0; i < 2; i++) {
        const int idx = i * 256 + tid;
        kv_kc[i]  = idx >> 3;
        kv_c8[i]  = idx & 7;
        kv_dst[i] = (uint32_t)((kv_kc[i] * PRH + kv_c8[i] * 8) * 2);
    }
    const uint32_t sk[2] = { smem_u32(Ksb[0]), smem_u32(Ksb[1]) };
    const uint32_t sv[2] = { smem_u32(Vsb[0]), smem_u32(Vsb[1]) };
    const uint32_t sq    = smem_u32(QP);

    // Precomputed ldmatrix address bases (lane-dependent, buffer-independent)
    const uint32_t aoff = (uint32_t)(((wq + a_row) * PRH) * 2);   // + (ks*16+a_kh)*2
    const uint32_t boff = (uint32_t)((b_row * PRH) * 2);          // + (ntp*16*PRH + ks*16+b_kh)*2

    for (int pass = 0; pass < 2; pass++) {
        const int it = pass ? p : (7 - p);
        const int q0 = it * AQT;

        __syncthreads();
        #pragma unroll
        for (int i = 0; i < 4; i++) {
            const int idx = i * 256 + tid;
            const int r = idx >> 3;
            const int c8 = idx & 7;
            CP_ASYNC16(sq + (uint32_t)((r * PRH + c8 * 8) * 2),
                       &Qb[(size_t)(q0 + r) * DD + c8 * 8]);
        }
        #pragma unroll
        for (int i = 0; i < 2; i++) {
            CP_ASYNC16(sk[0] + kv_dst[i], &Kb [(size_t)kv_kc[i] * DD + kv_c8[i] * 8]);
            CP_ASYNC16(sv[0] + kv_dst[i], &Vtb[(size_t)kv_kc[i] * LL + kv_c8[i] * 8]);
        }
        CP_COMMIT();
        CP_WAIT0();
        __syncthreads();

        // Build Q fragments via ldmatrix
        uint32_t qf[4][4];
        #pragma unroll
        for (int ks = 0; ks < 4; ks++)
            ldmatrix_x4(qf[ks][0], qf[ks][1], qf[ks][2], qf[ks][3],
                        sq + aoff + (uint32_t)((ks * 16 + a_kh) * 2));
        __syncthreads();   // QP becomes P buffer

        float oa[8][4];
        #pragma unroll
        for (int nt = 0; nt < 8; nt++)
            #pragma unroll
            for (int q = 0; q < 4; q++) oa[nt][q] = 0.0f;
        float m0v = -1e30f, m1v = -1e30f, l0 = 0.0f, l1 = 0.0f;

        const int jmax = 2 * it + 1;
        for (int jt = 0; jt <= jmax; jt++) {
            const int cur = jt & 1;

            if (jt < jmax) {
                const int nxt = cur ^ 1;
                const size_t kbase = (size_t)(jt + 1) * AKT;
                #pragma unroll
                for (int i = 0; i < 2; i++) {
                    CP_ASYNC16(sk[nxt] + kv_dst[i],
                               &Kb[(kbase + kv_kc[i]) * DD + kv_c8[i] * 8]);
                    CP_ASYNC16(sv[nxt] + kv_dst[i],
                               &Vtb[(size_t)kv_kc[i] * LL + kbase + kv_c8[i] * 8]);
                }
                CP_COMMIT();
            }

            // ---- S = Q K^T ----
            float sa2[8][4];
            #pragma unroll
            for (int nt = 0; nt < 8; nt++)
                #pragma unroll
                for (int q = 0; q < 4; q++) sa2[nt][q] = 0.0f;

            #pragma unroll
            for (int ks = 0; ks < 4; ks++) {
                uint32_t bf[8][2];
                #pragma unroll
                for (int ntp = 0; ntp < 4; ntp++) {
                    const uint32_t addr = sk[cur] + boff +
                        (uint32_t)((ntp * 16 * PRH + ks * 16 + b_kh) * 2);
                    ldmatrix_x4(bf[2 * ntp][0], bf[2 * ntp][1],
                                bf[2 * ntp + 1][0], bf[2 * ntp + 1][1], addr);
                }
                #pragma unroll
                for (int nt = 0; nt < 8; nt++)
                    mma_f16_16n8k16(sa2[nt][0], sa2[nt][1], sa2[nt][2], sa2[nt][3],
                                    qf[ks][0], qf[ks][1], qf[ks][2], qf[ks][3],
                                    bf[nt][0], bf[nt][1]);
            }

            // ---- Causal mask ----
            const int qg0 = q0 + wq + lr;
            const int qg1 = qg0 + 8;
            if (jt * AKT + AKT - 1 > q0 + wq) {
                #pragma unroll
                for (int nt = 0; nt < 8; nt++) {
                    const int kc0 = jt * AKT + nt * 8 + 2 * lc;
                    if (kc0     > qg0) sa2[nt][0] = -1e30f;
                    if (kc0 + 1 > qg0) sa2[nt][1] = -1e30f;
                    if (kc0     > qg1) sa2[nt][2] = -1e30f;
                    if (kc0 + 1 > qg1) sa2[nt][3] = -1e30f;
                }
            }

            // ---- Online softmax (log2 domain) ----
            float tmax0 = -1e30f, tmax1 = -1e30f;
            #pragma unroll
            for (int nt = 0; nt < 8; nt++) {
                tmax0 = fmaxf(tmax0, fmaxf(sa2[nt][0], sa2[nt][1]));
                tmax1 = fmaxf(tmax1, fmaxf(sa2[nt][2], sa2[nt][3]));
            }
            tmax0 = fmaxf(tmax0, __shfl_xor_sync(0xffffffffu, tmax0, 1));
            tmax0 = fmaxf(tmax0, __shfl_xor_sync(0xffffffffu, tmax0, 2));
            tmax1 = fmaxf(tmax1, __shfl_xor_sync(0xffffffffu, tmax1, 1));
            tmax1 = fmaxf(tmax1, __shfl_xor_sync(0xffffffffu, tmax1, 2));

            const float mn0 = fmaxf(m0v, tmax0);
            const float mn1 = fmaxf(m1v, tmax1);
            const float f0  = ex2f(m0v - mn0);
            const float f1  = ex2f(m1v - mn1);

            float rs0 = 0.0f, rs1 = 0.0f;
            #pragma unroll
            for (int nt = 0; nt < 8; nt++) {
                const float p00 = ex2f(sa2[nt][0] - mn0);
                const float p01 = ex2f(sa2[nt][1] - mn0);
                const float p10 = ex2f(sa2[nt][2] - mn1);
                const float p11 = ex2f(sa2[nt][3] - mn1);
                rs0 += p00 + p01;
                rs1 += p10 + p11;
                *(__half2*)&QP[(wq + lr    ) * PRH + nt * 8 + 2 * lc] = __floats2half2_rn(p00, p01);
                *(__half2*)&QP[(wq + lr + 8) * PRH + nt * 8 + 2 * lc] = __floats2half2_rn(p10, p11);
            }
            rs0 += __shfl_xor_sync(0xffffffffu, rs0, 1);
            rs0 += __shfl_xor_sync(0xffffffffu, rs0, 2);
            rs1 += __shfl_xor_sync(0xffffffffu, rs1, 1);
            rs1 += __shfl_xor_sync(0xffffffffu, rs1, 2);

            l0 = l0 * f0 + rs0;  m0v = mn0;
            l1 = l1 * f1 + rs1;  m1v = mn1;
            #pragma unroll
            for (int nt = 0; nt < 8; nt++) {
                oa[nt][0] *= f0;  oa[nt][1] *= f0;
                oa[nt][2] *= f1;  oa[nt][3] *= f1;
            }
            __syncwarp();

            // ---- O += P V ----
            #pragma unroll
            for (int ks = 0; ks < 4; ks++) {
                uint32_t pf[4];
                ldmatrix_x4(pf[0], pf[1], pf[2], pf[3],
                            sq + aoff + (uint32_t)((ks * 16 + a_kh) * 2));
                uint32_t vf[8][2];
                #pragma unroll
                for (int ntp = 0; ntp < 4; ntp++) {
                    const uint32_t addr = sv[cur] + boff +
                        (uint32_t)((ntp * 16 * PRH + ks * 16 + b_kh) * 2);
                    ldmatrix_x4(vf[2 * ntp][0], vf[2 * ntp][1],
                                vf[2 * ntp + 1][0], vf[2 * ntp + 1][1], addr);
                }
                #pragma unroll
                for (int nt = 0; nt < 8; nt++)
                    mma_f16_16n8k16(oa[nt][0], oa[nt][1], oa[nt][2], oa[nt][3],
                                    pf[0], pf[1], pf[2], pf[3],
                                    vf[nt][0], vf[nt][1]);
            }

            if (jt < jmax) CP_WAIT0();
            __syncthreads();
        }

        // ---- Epilogue (fp32 out) ----
        const float inv0 = 1.0f / l0;
        const float inv1 = 1.0f / l1;
        const int q1 = q0 + wq + lr;
        const int q2 = q1 + 8;
        #pragma unroll
        for (int nt = 0; nt < 8; nt++) {
            const int d = nt * 8 + 2 * lc;
            *(float2*)&out[((size_t)(b * LL + q1)) * DOUT + h * DD + d] =
                make_float2(oa[nt][0] * inv0, oa[nt][1] * inv0);
            *(float2*)&out[((size_t)(b * LL + q2)) * DOUT + h * DD + d] =
                make_float2(oa[nt][2] * inv1, oa[nt][3] * inv1);
        }
    }
}

// ---------------------------------------------------------------------------
extern "C" void kernel_launch(void* const* d_in, const int* in_sizes, int n_in,
                              void* d_out, int out_size)
{
    const float* Qseq = (const float*)d_in[0];
    const float* Kseq = (const float*)d_in[1];
    const float* Vseq = (const float*)d_in[2];
    const float* WQ   = (const float*)d_in[3];
    const float* WK   = (const float*)d_in[4];
    const float* WV   = (const float*)d_in[5];
    float* out = (float*)d_out;

    cudaFuncSetAttribute(proj_mma_kernel,
                         cudaFuncAttributeMaxDynamicSharedMemorySize, SMEM_PROJ);
    cudaFuncSetAttribute(attn_mma_kernel,
                         cudaFuncAttributeMaxDynamicSharedMemorySize, SMEM_ATTN);

    dim3 ppgrd(4096 + 256, 1, 3);
    prepass_kernel<<<ppgrd, 256>>>(Qseq, Kseq, Vseq, WQ, WK, WV);

    dim3 pgrd(DOUT / PTN, MM / PTM, 3);      // (4, 64, 3)
    proj_mma_kernel<<<pgrd, 256, SMEM_PROJ>>>();

    dim3 agrd(4, BB * HH);                   // 256 CTAs, one balanced wave
    attn_mma_kernel<<<agrd, 256, SMEM_ATTN>>>(out);
}

// round 11
// speedup vs baseline: 6.6065x; 1.0205x over previous
#include <cuda_runtime.h>
#include <cuda_fp16.h>
#include <cstdint>

// Problem constants
#define BB   8
#define LL   1024
#define DIN  512
#define HH   8
#define DD   64
#define DOUT 512
#define MM   (BB * LL)   // 8192

// Half-precision staging buffers
__device__ __half g_xh[3 * MM * DIN];       // inputs converted to half
__device__ __half g_wth[3 * DIN * DOUT];    // Wt[n][k] half; WQ pre-scaled by 0.125*log2e
__device__ __half g_q [BB * HH * LL * DD];  // [b,h,l,d], pre-scaled
__device__ __half g_k [BB * HH * LL * DD];  // [b,h,l,d]
__device__ __half g_vt[BB * HH * DD * LL];  // [b,h,d,l]  (V transposed)

// ===========================================================================
// Helpers
// ===========================================================================
__device__ __forceinline__ float ex2f(float x) {
    float y;
    asm("ex2.approx.ftz.f32 %0, %1;" : "=f"(y) : "f"(x));
    return y;
}

__device__ __forceinline__ void mma_f16_16n8k16(float& d0, float& d1, float& d2, float& d3,
                                                uint32_t a0, uint32_t a1, uint32_t a2, uint32_t a3,
                                                uint32_t b0, uint32_t b1) {
    asm volatile(
        "mma.sync.aligned.m16n8k16.row.col.f32.f16.f16.f32 "
        "{%0,%1,%2,%3}, {%4,%5,%6,%7}, {%8,%9}, {%0,%1,%2,%3};"
        : "+f"(d0), "+f"(d1), "+f"(d2), "+f"(d3)
        : "r"(a0), "r"(a1), "r"(a2), "r"(a3), "r"(b0), "r"(b1));
}

__device__ __forceinline__ void ldmatrix_x4(uint32_t& r0, uint32_t& r1,
                                            uint32_t& r2, uint32_t& r3, uint32_t addr) {
    asm volatile("ldmatrix.sync.aligned.m8n8.x4.shared.b16 {%0,%1,%2,%3}, [%4];"
                 : "=r"(r0), "=r"(r1), "=r"(r2), "=r"(r3) : "r"(addr));
}

__device__ __forceinline__ uint32_t smem_u32(const void* p) {
    uint32_t a;
    asm("{ .reg .u64 t; cvta.to.shared.u64 t, %1; cvt.u32.u64 %0, t; }"
        : "=r"(a) : "l"(p));
    return a;
}

__device__ __forceinline__ uint32_t h2u(__half2 h) {
    uint32_t u;
    asm("mov.b32 %0, %1;" : "=r"(u) : "r"(*(uint32_t*)&h));
    return u;
}

#define CP_ASYNC16(dst_u32, src_ptr) \
    asm volatile("cp.async.cg.shared.global [%0], [%1], 16;" :: "r"(dst_u32), "l"(src_ptr))
#define CP_COMMIT()  asm volatile("cp.async.commit_group;" ::: "memory")
#define CP_WAIT0()   asm volatile("cp.async.wait_group 0;" ::: "memory")

// ===========================================================================
// Fused pre-pass: convert X->half AND transpose/convert W, one launch.
// ===========================================================================
__global__ void prepass_kernel(const float* __restrict__ Q, const float* __restrict__ K,
                               const float* __restrict__ V,
                               const float* __restrict__ Wq, const float* __restrict__ Wk,
                               const float* __restrict__ Wv)
{
    const int z  = blockIdx.z;
    const int bx = blockIdx.x;
    const int tid = threadIdx.x;

    if (bx < 4096) {
        const float* src = (z == 0) ? Q : (z == 1) ? K : V;
        __half2* dst = (__half2*)(g_xh + (size_t)z * MM * DIN);
        const int i = bx * 256 + tid;
        const float4 v = ((const float4*)src)[i];
        dst[2 * i + 0] = __floats2half2_rn(v.x, v.y);
        dst[2 * i + 1] = __floats2half2_rn(v.z, v.w);
    } else {
        const float* W = (z == 0) ? Wq : (z == 1) ? Wk : Wv;
        __half* Wt = g_wth + (size_t)z * DIN * DOUT;
        const float s = (z == 0) ? 0.125f * 1.4426950408889634f : 1.0f;

        __shared__ float t[32][33];
        const int tile = bx - 4096;
        const int bxt  = tile & 15;
        const int byt  = tile >> 4;
        const int tx = tid & 31, ty = tid >> 5;
        int x = bxt * 32 + tx;
        int y = byt * 32 + ty;
        #pragma unroll
        for (int j = 0; j < 32; j += 8)
            t[ty + j][tx] = W[(size_t)(y + j) * DOUT + x];
        __syncthreads();
        x = byt * 32 + tx;
        y = bxt * 32 + ty;
        #pragma unroll
        for (int j = 0; j < 32; j += 8)
            Wt[(size_t)(y + j) * DIN + x] = __float2half(t[tx][ty + j] * s);
    }
}

// ===========================================================================
// fp16 mma.sync projection with ldmatrix fragment loads. (validated round 10)
// ===========================================================================
#define PTM 128
#define PTN 128
#define PTK 64
#define PKT (DIN / PTK)    // 8
#define PRH 72             // halves per smem row
#define PRW 36             // words per smem row
#define TILE_H (PTM * PRH)
#define SMEM_PROJ (4 * TILE_H * (int)sizeof(__half))   // 73728 B

__global__ __launch_bounds__(256)
void proj_mma_kernel()
{
    extern __shared__ __half smh[];
    __half* As[2] = { smh,              smh + TILE_H };
    __half* Bs[2] = { smh + 2 * TILE_H, smh + 3 * TILE_H };

    const int z = blockIdx.z;
    const __half* X  = g_xh  + (size_t)z * MM * DIN;
    const __half* Wt = g_wth + (size_t)z * DIN * DOUT;

    const int tid  = threadIdx.x;
    const int wid  = tid >> 5;
    const int lane = tid & 31;
    const int wm   = wid & 3;
    const int wn   = wid >> 2;
    const int m0   = blockIdx.y * PTM;
    const int n0   = blockIdx.x * PTN;
    const int lr   = lane >> 2;
    const int lc   = lane & 3;

    const int a_row = ((lane >> 3) & 1) * 8 + (lane & 7);
    const int a_kh  = (lane >> 4) * 8;
    const int b_row = (lane >> 4) * 8 + (lane & 7);
    const int b_kh  = ((lane >> 3) & 1) * 8;

    uint32_t dsto[4];
    const __half* a_src[4];
    const __half* b_src[4];
    #pragma unroll
    for (int i = 0; i < 4; i++) {
        const int idx = i * 256 + tid;
        const int r   = idx >> 3;
        const int c8  = idx & 7;
        dsto[i] = (uint32_t)((r * PRH + c8 * 8) * 2);
        a_src[i] = &X [(size_t)(m0 + r) * DIN + c8 * 8];
        b_src[i] = &Wt[(size_t)(n0 + r) * DIN + c8 * 8];
    }
    const uint32_t sa[2] = { smem_u32(As[0]), smem_u32(As[1]) };
    const uint32_t sb[2] = { smem_u32(Bs[0]), smem_u32(Bs[1]) };

    float acc[2][8][4];
    #pragma unroll
    for (int mt = 0; mt < 2; mt++)
        #pragma unroll
        for (int nt = 0; nt < 8; nt++)
            #pragma unroll
            for (int q = 0; q < 4; q++) acc[mt][nt][q] = 0.0f;

    #pragma unroll
    for (int i = 0; i < 4; i++) {
        CP_ASYNC16(sa[0] + dsto[i], a_src[i]);
        CP_ASYNC16(sb[0] + dsto[i], b_src[i]);
    }
    CP_COMMIT();
    CP_WAIT0();
    __syncthreads();

    for (int kt = 0; kt < PKT; kt++) {
        const int cur = kt & 1;
        if (kt + 1 < PKT) {
            const int nxt = cur ^ 1;
            const int koff = (kt + 1) * PTK;
            #pragma unroll
            for (int i = 0; i < 4; i++) {
                CP_ASYNC16(sa[nxt] + dsto[i], a_src[i] + koff);
                CP_ASYNC16(sb[nxt] + dsto[i], b_src[i] + koff);
            }
            CP_COMMIT();
        }

        const uint32_t Abase = sa[cur];
        const uint32_t Bbase = sb[cur];
        #pragma unroll
        for (int ks = 0; ks < 4; ks++) {
            uint32_t af[2][4];
            #pragma unroll
            for (int mt = 0; mt < 2; mt++) {
                const uint32_t addr = Abase +
                    (uint32_t)(((wm * 32 + mt * 16 + a_row) * PRH + ks * 16 + a_kh) * 2);
                ldmatrix_x4(af[mt][0], af[mt][1], af[mt][2], af[mt][3], addr);
            }
            uint32_t bf[8][2];
            #pragma unroll
            for (int ntp = 0; ntp < 4; ntp++) {
                const uint32_t addr = Bbase +
                    (uint32_t)(((wn * 64 + ntp * 16 + b_row) * PRH + ks * 16 + b_kh) * 2);
                ldmatrix_x4(bf[2 * ntp][0], bf[2 * ntp][1],
                            bf[2 * ntp + 1][0], bf[2 * ntp + 1][1], addr);
            }
            #pragma unroll
            for (int mt = 0; mt < 2; mt++)
                #pragma unroll
                for (int nt = 0; nt < 8; nt++)
                    mma_f16_16n8k16(acc[mt][nt][0], acc[mt][nt][1],
                                    acc[mt][nt][2], acc[mt][nt][3],
                                    af[mt][0], af[mt][1], af[mt][2], af[mt][3],
                                    bf[nt][0], bf[nt][1]);
        }

        if (kt + 1 < PKT) CP_WAIT0();
        __syncthreads();
    }

    if (z < 2) {
        __half* out = (z == 0) ? g_q : g_k;
        #pragma unroll
        for (int mt = 0; mt < 2; mt++) {
            #pragma unroll
            for (int nt = 0; nt < 8; nt++) {
                const int n  = n0 + wn * 64 + nt * 8 + 2 * lc;
                const int h  = n >> 6;
                const int d  = n & 63;
                const int m1 = m0 + wm * 32 + mt * 16 + lr;
                const int b1 = m1 >> 10, l1 = m1 & 1023;
                *(__half2*)&out[(((size_t)(b1 * HH + h) * LL + l1) * DD) + d] =
                    __floats2half2_rn(acc[mt][nt][0], acc[mt][nt][1]);
                const int m2 = m1 + 8;
                const int b2 = m2 >> 10, l2 = m2 & 1023;
                *(__half2*)&out[(((size_t)(b2 * HH + h) * LL + l2) * DD) + d] =
                    __floats2half2_rn(acc[mt][nt][2], acc[mt][nt][3]);
            }
        }
    } else {
        #pragma unroll
        for (int mt = 0; mt < 2; mt++) {
            #pragma unroll
            for (int nt = 0; nt < 8; nt++) {
                const int n  = n0 + wn * 64 + nt * 8 + 2 * lc;
                const int h  = n >> 6;
                const int d  = n & 63;
                const int m1 = m0 + wm * 32 + mt * 16 + lr;
                const int b1 = m1 >> 10, l1 = m1 & 1023;
                __half* base1 = &g_vt[((size_t)(b1 * HH + h) * DD + d) * LL + l1];
                base1[0]  = __float2half(acc[mt][nt][0]);
                base1[LL] = __float2half(acc[mt][nt][1]);
                const int m2 = m1 + 8;
                const int b2 = m2 >> 10, l2 = m2 & 1023;
                __half* base2 = &g_vt[((size_t)(b2 * HH + h) * DD + d) * LL + l2];
                base2[0]  = __float2half(acc[mt][nt][2]);
                base2[LL] = __float2half(acc[mt][nt][3]);
            }
        }
    }
}

// ===========================================================================
// Flash attention, fp16 m16n8k16 + ldmatrix, balanced q-tile pairing.
// P never touches smem: the S-accumulator fragment layout equals the PV
// A-fragment layout, so exp'd probabilities are packed straight into
// registers (pf[kk] from S n-tiles {2kk, 2kk+1}).
// ===========================================================================
#define AQT  128
#define AKT  64
#define KVH  (AKT * PRH)
#define QPH  (AQT * PRH)
#define SMEM_ATTN ((4 * KVH + QPH) * (int)sizeof(__half))   // 55296 B

__global__ __launch_bounds__(256, 2)
void attn_mma_kernel(float* __restrict__ out)
{
    extern __shared__ __half smh[];
    __half* Ksb[2] = { smh,           smh + KVH };
    __half* Vsb[2] = { smh + 2 * KVH, smh + 3 * KVH };
    __half* QP     = smh + 4 * KVH;     // Q staging only

    const int p  = blockIdx.x;          // 0..3
    const int bh = blockIdx.y;
    const int b  = bh >> 3;
    const int h  = bh & 7;

    const __half* Qb  = g_q  + (size_t)bh * LL * DD;
    const __half* Kb  = g_k  + (size_t)bh * LL * DD;
    const __half* Vtb = g_vt + (size_t)bh * DD * LL;

    const int tid  = threadIdx.x;
    const int wid  = tid >> 5;
    const int lane = tid & 31;
    const int lr   = lane >> 2;
    const int lc   = lane & 3;
    const int wq   = wid * 16;

    const int a_row = ((lane >> 3) & 1) * 8 + (lane & 7);
    const int a_kh  = (lane >> 4) * 8;
    const int b_row = (lane >> 4) * 8 + (lane & 7);
    const int b_kh  = ((lane >> 3) & 1) * 8;

    uint32_t kv_dst[2];
    int kv_kc[2], kv_c8[2];
    #pragma unroll
    for (int i = 0; i < 2; i++) {
        const int idx = i * 256 + tid;
        kv_kc[i]  = idx >> 3;
        kv_c8[i]  = idx & 7;
        kv_dst[i] = (uint32_t)((kv_kc[i] * PRH + kv_c8[i] * 8) * 2);
    }
    const uint32_t sk[2] = { smem_u32(Ksb[0]), smem_u32(Ksb[1]) };
    const uint32_t sv[2] = { smem_u32(Vsb[0]), smem_u32(Vsb[1]) };
    const uint32_t sq    = smem_u32(QP);

    const uint32_t aoff = (uint32_t)(((wq + a_row) * PRH) * 2);
    const uint32_t boff = (uint32_t)((b_row * PRH) * 2);

    for (int pass = 0; pass < 2; pass++) {
        const int it = pass ? p : (7 - p);
        const int q0 = it * AQT;

        __syncthreads();
        #pragma unroll
        for (int i = 0; i < 4; i++) {
            const int idx = i * 256 + tid;
            const int r = idx >> 3;
            const int c8 = idx & 7;
            CP_ASYNC16(sq + (uint32_t)((r * PRH + c8 * 8) * 2),
                       &Qb[(size_t)(q0 + r) * DD + c8 * 8]);
        }
        #pragma unroll
        for (int i = 0; i < 2; i++) {
            CP_ASYNC16(sk[0] + kv_dst[i], &Kb [(size_t)kv_kc[i] * DD + kv_c8[i] * 8]);
            CP_ASYNC16(sv[0] + kv_dst[i], &Vtb[(size_t)kv_kc[i] * LL + kv_c8[i] * 8]);
        }
        CP_COMMIT();
        CP_WAIT0();
        __syncthreads();

        // Build Q fragments via ldmatrix
        uint32_t qf[4][4];
        #pragma unroll
        for (int ks = 0; ks < 4; ks++)
            ldmatrix_x4(qf[ks][0], qf[ks][1], qf[ks][2], qf[ks][3],
                        sq + aoff + (uint32_t)((ks * 16 + a_kh) * 2));

        float oa[8][4];
        #pragma unroll
        for (int nt = 0; nt < 8; nt++)
            #pragma unroll
            for (int q = 0; q < 4; q++) oa[nt][q] = 0.0f;
        float m0v = -1e30f, m1v = -1e30f, l0 = 0.0f, l1 = 0.0f;

        const int jmax = 2 * it + 1;
        for (int jt = 0; jt <= jmax; jt++) {
            const int cur = jt & 1;

            if (jt < jmax) {
                const int nxt = cur ^ 1;
                const size_t kbase = (size_t)(jt + 1) * AKT;
                #pragma unroll
                for (int i = 0; i < 2; i++) {
                    CP_ASYNC16(sk[nxt] + kv_dst[i],
                               &Kb[(kbase + kv_kc[i]) * DD + kv_c8[i] * 8]);
                    CP_ASYNC16(sv[nxt] + kv_dst[i],
                               &Vtb[(size_t)kv_kc[i] * LL + kbase + kv_c8[i] * 8]);
                }
                CP_COMMIT();
            }

            // ---- S = Q K^T ----
            float sa2[8][4];
            #pragma unroll
            for (int nt = 0; nt < 8; nt++)
                #pragma unroll
                for (int q = 0; q < 4; q++) sa2[nt][q] = 0.0f;

            #pragma unroll
            for (int ks = 0; ks < 4; ks++) {
                uint32_t bf[8][2];
                #pragma unroll
                for (int ntp = 0; ntp < 4; ntp++) {
                    const uint32_t addr = sk[cur] + boff +
                        (uint32_t)((ntp * 16 * PRH + ks * 16 + b_kh) * 2);
                    ldmatrix_x4(bf[2 * ntp][0], bf[2 * ntp][1],
                                bf[2 * ntp + 1][0], bf[2 * ntp + 1][1], addr);
                }
                #pragma unroll
                for (int nt = 0; nt < 8; nt++)
                    mma_f16_16n8k16(sa2[nt][0], sa2[nt][1], sa2[nt][2], sa2[nt][3],
                                    qf[ks][0], qf[ks][1], qf[ks][2], qf[ks][3],
                                    bf[nt][0], bf[nt][1]);
            }

            // ---- Causal mask ----
            const int qg0 = q0 + wq + lr;
            const int qg1 = qg0 + 8;
            if (jt * AKT + AKT - 1 > q0 + wq) {
                #pragma unroll
                for (int nt = 0; nt < 8; nt++) {
                    const int kc0 = jt * AKT + nt * 8 + 2 * lc;
                    if (kc0     > qg0) sa2[nt][0] = -1e30f;
                    if (kc0 + 1 > qg0) sa2[nt][1] = -1e30f;
                    if (kc0     > qg1) sa2[nt][2] = -1e30f;
                    if (kc0 + 1 > qg1) sa2[nt][3] = -1e30f;
                }
            }

            // ---- Online softmax (log2 domain); P packed straight to frags ----
            float tmax0 = -1e30f, tmax1 = -1e30f;
            #pragma unroll
            for (int nt = 0; nt < 8; nt++) {
                tmax0 = fmaxf(tmax0, fmaxf(sa2[nt][0], sa2[nt][1]));
                tmax1 = fmaxf(tmax1, fmaxf(sa2[nt][2], sa2[nt][3]));
            }
            tmax0 = fmaxf(tmax0, __shfl_xor_sync(0xffffffffu, tmax0, 1));
            tmax0 = fmaxf(tmax0, __shfl_xor_sync(0xffffffffu, tmax0, 2));
            tmax1 = fmaxf(tmax1, __shfl_xor_sync(0xffffffffu, tmax1, 1));
            tmax1 = fmaxf(tmax1, __shfl_xor_sync(0xffffffffu, tmax1, 2));

            const float mn0 = fmaxf(m0v, tmax0);
            const float mn1 = fmaxf(m1v, tmax1);
            const float f0  = ex2f(m0v - mn0);
            const float f1  = ex2f(m1v - mn1);

            // pf[kk] = A-fragment of P for k-block kk, built from S n-tiles
            // {2kk, 2kk+1}:  a0=(row lr), a1=(row lr+8) of nt=2kk;
            //                a2=(row lr), a3=(row lr+8) of nt=2kk+1.
            uint32_t pf[4][4];
            float rs0 = 0.0f, rs1 = 0.0f;
            #pragma unroll
            for (int nt = 0; nt < 8; nt++) {
                const float p00 = ex2f(sa2[nt][0] - mn0);
                const float p01 = ex2f(sa2[nt][1] - mn0);
                const float p10 = ex2f(sa2[nt][2] - mn1);
                const float p11 = ex2f(sa2[nt][3] - mn1);
                rs0 += p00 + p01;
                rs1 += p10 + p11;
                const int kk  = nt >> 1;
                const int sub = (nt & 1) * 2;
                pf[kk][sub + 0] = h2u(__floats2half2_rn(p00, p01));
                pf[kk][sub + 1] = h2u(__floats2half2_rn(p10, p11));
            }
            rs0 += __shfl_xor_sync(0xffffffffu, rs0, 1);
            rs0 += __shfl_xor_sync(0xffffffffu, rs0, 2);
            rs1 += __shfl_xor_sync(0xffffffffu, rs1, 1);
            rs1 += __shfl_xor_sync(0xffffffffu, rs1, 2);

            l0 = l0 * f0 + rs0;  m0v = mn0;
            l1 = l1 * f1 + rs1;  m1v = mn1;
            #pragma unroll
            for (int nt = 0; nt < 8; nt++) {
                oa[nt][0] *= f0;  oa[nt][1] *= f0;
                oa[nt][2] *= f1;  oa[nt][3] *= f1;
            }

            // ---- O += P V  (pf from registers; vf via ldmatrix) ----
            #pragma unroll
            for (int ks = 0; ks < 4; ks++) {
                uint32_t vf[8][2];
                #pragma unroll
                for (int ntp = 0; ntp < 4; ntp++) {
                    const uint32_t addr = sv[cur] + boff +
                        (uint32_t)((ntp * 16 * PRH + ks * 16 + b_kh) * 2);
                    ldmatrix_x4(vf[2 * ntp][0], vf[2 * ntp][1],
                                vf[2 * ntp + 1][0], vf[2 * ntp + 1][1], addr);
                }
                #pragma unroll
                for (int nt = 0; nt < 8; nt++)
                    mma_f16_16n8k16(oa[nt][0], oa[nt][1], oa[nt][2], oa[nt][3],
                                    pf[ks][0], pf[ks][1], pf[ks][2], pf[ks][3],
                                    vf[nt][0], vf[nt][1]);
            }

            if (jt < jmax) CP_WAIT0();
            __syncthreads();
        }

        // ---- Epilogue (fp32 out) ----
        const float inv0 = 1.0f / l0;
        const float inv1 = 1.0f / l1;
        const int q1 = q0 + wq + lr;
        const int q2 = q1 + 8;
        #pragma unroll
        for (int nt = 0; nt < 8; nt++) {
            const int d = nt * 8 + 2 * lc;
            *(float2*)&out[((size_t)(b * LL + q1)) * DOUT + h * DD + d] =
                make_float2(oa[nt][0] * inv0, oa[nt][1] * inv0);
            *(float2*)&out[((size_t)(b * LL + q2)) * DOUT + h * DD + d] =
                make_float2(oa[nt][2] * inv1, oa[nt][3] * inv1);
        }
    }
}

// ---------------------------------------------------------------------------
extern "C" void kernel_launch(void* const* d_in, const int* in_sizes, int n_in,
                              void* d_out, int out_size)
{
    const float* Qseq = (const float*)d_in[0];
    const float* Kseq = (const float*)d_in[1];
    const float* Vseq = (const float*)d_in[2];
    const float* WQ   = (const float*)d_in[3];
    const float* WK   = (const float*)d_in[4];
    const float* WV   = (const float*)d_in[5];
    float* out = (float*)d_out;

    cudaFuncSetAttribute(proj_mma_kernel,
                         cudaFuncAttributeMaxDynamicSharedMemorySize, SMEM_PROJ);
    cudaFuncSetAttribute(attn_mma_kernel,
                         cudaFuncAttributeMaxDynamicSharedMemorySize, SMEM_ATTN);

    dim3 ppgrd(4096 + 256, 1, 3);
    prepass_kernel<<<ppgrd, 256>>>(Qseq, Kseq, Vseq, WQ, WK, WV);

    dim3 pgrd(DOUT / PTN, MM / PTM, 3);      // (4, 64, 3)
    proj_mma_kernel<<<pgrd, 256, SMEM_PROJ>>>();

    dim3 agrd(4, BB * HH);                   // 256 CTAs, one balanced wave
    attn_mma_kernel<<<agrd, 256, SMEM_ATTN>>>(out);
}